// round 15
// baseline (speedup 1.0000x reference)
#include <cuda_runtime.h>
#include <cuda_bf16.h>
#include <math.h>

#define SEQ 4096
#define DMODEL 512
#define NHEAD 8
#define FDIM 2048
#define NEXP 8
#define NPAIR (SEQ * 2)
#define MAXTILE 80

// ---------------- scratch (device globals; no allocations allowed) ----------
__device__ float g_xn[SEQ * DMODEL];
__device__ __nv_bfloat16 g_xnb[SEQ * DMODEL];
__device__ __nv_bfloat16 g_qkvb[SEQ * 3 * DMODEL];
__device__ __nv_bfloat16 g_attnb[SEQ * DMODEL];
__device__ __nv_bfloat16 g_h1b[NPAIR * FDIM];
__device__ __nv_bfloat16 g_hb[NPAIR * FDIM];
__device__ float g_dout[NPAIR * DMODEL];
__device__ __nv_bfloat16 g_bwin[3 * DMODEL * DMODEL];
__device__ __nv_bfloat16 g_bwout[DMODEL * DMODEL];
__device__ __nv_bfloat16 g_bw1[NEXP * FDIM * DMODEL];
__device__ __nv_bfloat16 g_bw2[NEXP * FDIM * DMODEL];
__device__ __nv_bfloat16 g_bwo[NEXP * DMODEL * FDIM];
__device__ int   g_tidx[NPAIR];
__device__ float g_tscale[NPAIR];
__device__ int   g_counts[NEXP];
__device__ int   g_cursor[NEXP];
__device__ int   g_off[NEXP];
__device__ float g_rowScale[NPAIR];
__device__ int   g_rowTok[NPAIR];
__device__ int   g_pairRow[NPAIR];
__device__ int   g_tileE[MAXTILE];
__device__ int   g_tileBm[MAXTILE];
__device__ int   g_ntiles;

// ---------------- helpers -----------------------------------------------------
__device__ __forceinline__ void mma16(float c[4],
    unsigned a0, unsigned a1, unsigned a2, unsigned a3,
    unsigned b0, unsigned b1)
{
    asm volatile(
        "mma.sync.aligned.m16n8k16.row.col.f32.bf16.bf16.f32 "
        "{%0,%1,%2,%3}, {%4,%5,%6,%7}, {%8,%9}, {%0,%1,%2,%3};\n"
        : "+f"(c[0]), "+f"(c[1]), "+f"(c[2]), "+f"(c[3])
        : "r"(a0), "r"(a1), "r"(a2), "r"(a3), "r"(b0), "r"(b1));
}

__device__ __forceinline__ void ldsm4(unsigned& r0, unsigned& r1,
                                      unsigned& r2, unsigned& r3, unsigned addr)
{
    asm volatile(
        "ldmatrix.sync.aligned.m8n8.x4.shared.b16 {%0,%1,%2,%3}, [%4];\n"
        : "=r"(r0), "=r"(r1), "=r"(r2), "=r"(r3) : "r"(addr));
}

__device__ __forceinline__ void ldsm4t(unsigned& r0, unsigned& r1,
                                       unsigned& r2, unsigned& r3, unsigned addr)
{
    asm volatile(
        "ldmatrix.sync.aligned.m8n8.x4.trans.shared.b16 {%0,%1,%2,%3}, [%4];\n"
        : "=r"(r0), "=r"(r1), "=r"(r2), "=r"(r3) : "r"(addr));
}

__device__ __forceinline__ unsigned smem_u32(const void* p) {
    return (unsigned)__cvta_generic_to_shared(p);
}
__device__ __forceinline__ void cpa16(unsigned dst, const void* src, int vbytes) {
    asm volatile("cp.async.cg.shared.global [%0], [%1], 16, %2;\n"
                 :: "r"(dst), "l"(src), "r"(vbytes) : "memory");
}
__device__ __forceinline__ void cpa_commit() {
    asm volatile("cp.async.commit_group;\n" ::: "memory");
}
__device__ __forceinline__ unsigned packbf(float a, float b) {
    __nv_bfloat162 p = __floats2bfloat162_rn(a, b);
    return *(unsigned*)&p;
}

#define LDSM_OFFS() \
    const int rl_ = lane & 7, quad_ = lane >> 3; \
    const int arow_off = rl_ + ((quad_ & 1) << 3); \
    const int acol_off = (quad_ >> 1) << 2; \
    const int brow_off = rl_ + ((quad_ >> 1) << 3); \
    const int bcol_off = (quad_ & 1) << 2;

// ---------------- fused fp32 -> bf16 convert, block-uniform regions -----------
// block = 2048 float4. Regions (blocks): bwin[0,96) bwout[96,128)
// w1[128,1152) w2[1152,2176) wo[2176,3200).
__global__ __launch_bounds__(256) void f2bf_all(
    const float* __restrict__ w_in, const float* __restrict__ w_out,
    const float* __restrict__ w1, const float* __restrict__ w2,
    const float* __restrict__ wo)
{
    int blk = blockIdx.x;
    const float4* src;
    uint2* dst;
    size_t base;
    if (blk < 96)        { src = (const float4*)w_in;  dst = (uint2*)g_bwin;  base = (size_t)blk * 2048; }
    else if (blk < 128)  { src = (const float4*)w_out; dst = (uint2*)g_bwout; base = (size_t)(blk - 96) * 2048; }
    else if (blk < 1152) { src = (const float4*)w1;    dst = (uint2*)g_bw1;   base = (size_t)(blk - 128) * 2048; }
    else if (blk < 2176) { src = (const float4*)w2;    dst = (uint2*)g_bw2;   base = (size_t)(blk - 1152) * 2048; }
    else                 { src = (const float4*)wo;    dst = (uint2*)g_bwo;   base = (size_t)(blk - 2176) * 2048; }
    size_t i0 = base + threadIdx.x;
    float4 v[8];
    #pragma unroll
    for (int j = 0; j < 8; j++) v[j] = src[i0 + j * 256];
    #pragma unroll
    for (int j = 0; j < 8; j++) {
        uint2 u; u.x = packbf(v[j].x, v[j].y); u.y = packbf(v[j].z, v[j].w);
        dst[i0 + j * 256] = u;
    }
}

// ---------------- layernorm (dual fp32 + bf16 output) -------------------------
__global__ __launch_bounds__(128) void layernorm_k(
    const float* __restrict__ x, const float* __restrict__ g,
    const float* __restrict__ b, float* __restrict__ y,
    __nv_bfloat16* __restrict__ yb)
{
    int t = blockIdx.x;
    int tid = threadIdx.x;
    float4 v = ((const float4*)(x + (size_t)t * DMODEL))[tid];
    float s  = v.x + v.y + v.z + v.w;
    float ss = v.x * v.x + v.y * v.y + v.z * v.z + v.w * v.w;
    #pragma unroll
    for (int o = 16; o > 0; o >>= 1) {
        s  += __shfl_xor_sync(0xffffffffu, s, o);
        ss += __shfl_xor_sync(0xffffffffu, ss, o);
    }
    __shared__ float sw[4], ssw[4];
    __shared__ float meanS, rstdS;
    int lane = tid & 31, w = tid >> 5;
    if (lane == 0) { sw[w] = s; ssw[w] = ss; }
    __syncthreads();
    if (tid == 0) {
        float S = sw[0] + sw[1] + sw[2] + sw[3];
        float SS = ssw[0] + ssw[1] + ssw[2] + ssw[3];
        float mean = S / (float)DMODEL;
        float var = SS / (float)DMODEL - mean * mean;
        meanS = mean;
        rstdS = rsqrtf(var + 1e-5f);
    }
    __syncthreads();
    float mean = meanS, rstd = rstdS;
    float4 gg = ((const float4*)g)[tid];
    float4 bb = ((const float4*)b)[tid];
    float4 o;
    o.x = (v.x - mean) * rstd * gg.x + bb.x;
    o.y = (v.y - mean) * rstd * gg.y + bb.y;
    o.z = (v.z - mean) * rstd * gg.z + bb.z;
    o.w = (v.w - mean) * rstd * gg.w + bb.w;
    ((float4*)(y + (size_t)t * DMODEL))[tid] = o;
    uint2 u; u.x = packbf(o.x, o.y); u.y = packbf(o.z, o.w);
    ((uint2*)(yb + (size_t)t * DMODEL))[tid] = u;
}

// ---------------- bf16 GEMM core: BK=64, 3 stages, ONE sync per 64-k chunk ----
// BM=BN=128, 256 threads (8 warps 2x4), warp tile 64x32, m16n8k16.
// Row = 64 bf16 = 32 uints + 4 pad (stride 36, conflict-free ldsm).
// Stage = A(18432B) + B(18432B) = 36864B; 3 stages = 110592B dynamic.
#define GEMM_STAGE_BYTES 36864
#define GEMM_SMEM_BYTES (3 * GEMM_STAGE_BYTES)

__device__ __forceinline__ void gemm_bf16_core(
    const __nv_bfloat16* __restrict__ Ar, int av,
    const __nv_bfloat16* __restrict__ B,
    int K, int bn, unsigned* su, float c[4][4][4])
{
    const int tid = threadIdx.x;
    const int lane = tid & 31;
    const int w = tid >> 5, wm = (w >> 2) << 6, wn = (w & 3) << 5;
    LDSM_OFFS();
    const int r = tid >> 1;
    const int seg0 = (tid & 1) << 2;   // 0 or 4 (4 x 16B segs each)
    const int nk = K >> 6;
    const __nv_bfloat16* Br = B + (size_t)(bn + r) * K;
    const unsigned suB = smem_u32(su);
    const unsigned dstA0 = suB + (unsigned)(r * 36) * 4;

    #define GEMM_ISSUE(kt_, st_) do {                                          \
        int k0_ = (kt_) << 6;                                                  \
        unsigned sb_ = (unsigned)(st_) * GEMM_STAGE_BYTES;                     \
        _Pragma("unroll")                                                      \
        for (int i_ = 0; i_ < 4; i_++) {                                       \
            int seg_ = seg0 + i_;                                              \
            cpa16(dstA0 + sb_ + seg_ * 16, Ar + k0_ + seg_ * 8, av);           \
            cpa16(dstA0 + sb_ + 18432 + seg_ * 16, Br + k0_ + seg_ * 8, 16);   \
        }                                                                      \
        cpa_commit();                                                          \
    } while (0)

    GEMM_ISSUE(0, 0);
    if (nk > 1) GEMM_ISSUE(1, 1);

    int stC = 0, stI = 2;
    for (int kt = 0; kt < nk; kt++) {
        if (kt < nk - 1) asm volatile("cp.async.wait_group 1;\n" ::: "memory");
        else             asm volatile("cp.async.wait_group 0;\n" ::: "memory");
        __syncthreads();           // all warps done with stage stI's old chunk
        if (kt + 2 < nk) GEMM_ISSUE(kt + 2, stI);
        const unsigned stageA = suB + (unsigned)stC * GEMM_STAGE_BYTES;
        const unsigned stageB = stageA + 18432u;
        #pragma unroll
        for (int kk = 0; kk < 4; kk++) {
            const int kb = kk << 3;
            unsigned a[4][4], b[4][2];
            const unsigned aAddr =
                stageA + (unsigned)((wm + arow_off) * 36 + kb + acol_off) * 4;
            #pragma unroll
            for (int mi = 0; mi < 4; mi++)
                ldsm4(a[mi][0], a[mi][1], a[mi][2], a[mi][3],
                      aAddr + (unsigned)(mi * 16 * 36) * 4);
            const unsigned bAddr =
                stageB + (unsigned)((wn + brow_off) * 36 + kb + bcol_off) * 4;
            ldsm4(b[0][0], b[0][1], b[1][0], b[1][1], bAddr);
            ldsm4(b[2][0], b[2][1], b[3][0], b[3][1],
                  bAddr + (unsigned)(16 * 36) * 4);
            #pragma unroll
            for (int mi = 0; mi < 4; mi++)
                #pragma unroll
                for (int ni = 0; ni < 4; ni++)
                    mma16(c[mi][ni], a[mi][0], a[mi][1], a[mi][2], a[mi][3],
                          b[ni][0], b[ni][1]);
        }
        stC = (stC == 2) ? 0 : stC + 1;
        stI = (stI == 2) ? 0 : stI + 1;
    }
    #undef GEMM_ISSUE
}

#define GEMM_PROLOGUE() \
    extern __shared__ unsigned su[]; \
    float c[4][4][4]; \
    _Pragma("unroll") \
    for (int mi = 0; mi < 4; mi++) \
        _Pragma("unroll") \
        for (int ni = 0; ni < 4; ni++) \
            _Pragma("unroll") \
            for (int j = 0; j < 4; j++) c[mi][ni][j] = 0.f; \
    const int lane = threadIdx.x & 31; \
    const int g = lane >> 2, tig = lane & 3; \
    const int w = threadIdx.x >> 5; \
    const int wm = (w >> 2) << 6, wn = (w & 3) << 5;

#define DENSE_AROW(Abase, Kd) \
    const int r_ = threadIdx.x >> 1; \
    const int arow_ = (bm + r_ < M) ? (bm + r_) : 0; \
    const int av = (bm + r_ < M) ? 16 : 0; \
    const __nv_bfloat16* Ar = (Abase) + (size_t)arow_ * (Kd);

__global__ __launch_bounds__(256, 2) void gemm_bf16_nt(
    const __nv_bfloat16* __restrict__ A, const __nv_bfloat16* __restrict__ B,
    const float* __restrict__ bias, const float* __restrict__ resid,
    float* __restrict__ C, int M, int N, int K)
{
    const int bm = blockIdx.y * 128;
    const int bn = blockIdx.x * 128;
    GEMM_PROLOGUE();
    DENSE_AROW(A, K);
    gemm_bf16_core(Ar, av, B, K, bn, su, c);
    #pragma unroll
    for (int mi = 0; mi < 4; mi++)
        #pragma unroll
        for (int half = 0; half < 2; half++) {
            int row = bm + wm + (mi << 4) + g + half * 8;
            if (row >= M) continue;
            #pragma unroll
            for (int ni = 0; ni < 4; ni++) {
                int col = bn + wn + (ni << 3) + 2 * tig;
                float v0 = c[mi][ni][half * 2]     + bias[col];
                float v1 = c[mi][ni][half * 2 + 1] + bias[col + 1];
                if (resid) {
                    v0 += resid[(size_t)row * N + col];
                    v1 += resid[(size_t)row * N + col + 1];
                }
                float2 v; v.x = v0; v.y = v1;
                *(float2*)&C[(size_t)row * N + col] = v;
            }
        }
}

__global__ __launch_bounds__(256, 2) void gemm_qkv(
    const __nv_bfloat16* __restrict__ A, const __nv_bfloat16* __restrict__ B,
    const float* __restrict__ bias, __nv_bfloat16* __restrict__ C,
    int M, int N, int K)
{
    const int bm = blockIdx.y * 128;
    const int bn = blockIdx.x * 128;
    GEMM_PROLOGUE();
    DENSE_AROW(A, K);
    gemm_bf16_core(Ar, av, B, K, bn, su, c);
    #pragma unroll
    for (int mi = 0; mi < 4; mi++)
        #pragma unroll
        for (int half = 0; half < 2; half++) {
            int row = bm + wm + (mi << 4) + g + half * 8;
            #pragma unroll
            for (int ni = 0; ni < 4; ni++) {
                int col = bn + wn + (ni << 3) + 2 * tig;
                float sc = (col < DMODEL) ? 0.125f : 1.f;
                float v0 = (c[mi][ni][half * 2]     + bias[col]) * sc;
                float v1 = (c[mi][ni][half * 2 + 1] + bias[col + 1]) * sc;
                *(unsigned*)&C[(size_t)row * N + col] = packbf(v0, v1);
            }
        }
}

#define MOE_AROW() \
    const int r_ = threadIdx.x >> 1; \
    const bool vld_ = (bm + r_ < M); \
    const int tok_ = vld_ ? g_rowTok[g_off[e] + bm + r_] : 0; \
    const int av = vld_ ? 16 : 0; \
    const __nv_bfloat16* Ar = g_xnb + (size_t)tok_ * DMODEL;

__global__ __launch_bounds__(256, 2) void moe_up1(const float* __restrict__ Ball)
{
    int ti = blockIdx.y;
    if (ti >= g_ntiles) return;
    int e = g_tileE[ti];
    int bm = g_tileBm[ti];
    int M = g_counts[e];
    int bn = blockIdx.x * 128;
    const __nv_bfloat16* B = g_bw1 + (size_t)e * FDIM * DMODEL;
    const float* bias = Ball + (size_t)e * FDIM;
    __nv_bfloat16* C = g_h1b + (size_t)g_off[e] * FDIM;
    GEMM_PROLOGUE();
    MOE_AROW();
    gemm_bf16_core(Ar, av, B, DMODEL, bn, su, c);
    #pragma unroll
    for (int mi = 0; mi < 4; mi++)
        #pragma unroll
        for (int half = 0; half < 2; half++) {
            int row = bm + wm + (mi << 4) + g + half * 8;
            if (row >= M) continue;
            #pragma unroll
            for (int ni = 0; ni < 4; ni++) {
                int col = bn + wn + (ni << 3) + 2 * tig;
                *(unsigned*)&C[(size_t)row * FDIM + col] =
                    packbf(c[mi][ni][half * 2]     + bias[col],
                           c[mi][ni][half * 2 + 1] + bias[col + 1]);
            }
        }
}

__global__ __launch_bounds__(256, 2) void moe_up2(const float* __restrict__ Ball)
{
    int ti = blockIdx.y;
    if (ti >= g_ntiles) return;
    int e = g_tileE[ti];
    int bm = g_tileBm[ti];
    int M = g_counts[e];
    int bn = blockIdx.x * 128;
    const __nv_bfloat16* B = g_bw2 + (size_t)e * FDIM * DMODEL;
    const float* bias = Ball + (size_t)e * FDIM;
    const __nv_bfloat16* H1 = g_h1b + (size_t)g_off[e] * FDIM;
    __nv_bfloat16* HB = g_hb + (size_t)g_off[e] * FDIM;
    GEMM_PROLOGUE();
    MOE_AROW();
    gemm_bf16_core(Ar, av, B, DMODEL, bn, su, c);
    #pragma unroll
    for (int mi = 0; mi < 4; mi++)
        #pragma unroll
        for (int half = 0; half < 2; half++) {
            int row = bm + wm + (mi << 4) + g + half * 8;
            if (row >= M) continue;
            #pragma unroll
            for (int ni = 0; ni < 4; ni++) {
                int col = bn + wn + (ni << 3) + 2 * tig;
                unsigned hv = *(const unsigned*)&H1[(size_t)row * FDIM + col];
                __nv_bfloat162 hb2 = *(__nv_bfloat162*)&hv;
                float gx = __bfloat162float(hb2.x);
                float gy = __bfloat162float(hb2.y);
                float h2v0 = c[mi][ni][half * 2]     + bias[col];
                float h2v1 = c[mi][ni][half * 2 + 1] + bias[col + 1];
                float s0 = gx / (1.f + __expf(-gx));
                float s1 = gy / (1.f + __expf(-gy));
                *(unsigned*)&HB[(size_t)row * FDIM + col] = packbf(s0 * h2v0, s1 * h2v1);
            }
        }
}

__global__ __launch_bounds__(256, 2) void moe_down(const float* __restrict__ Bo)
{
    int ti = blockIdx.y;
    if (ti >= g_ntiles) return;
    int e = g_tileE[ti];
    int bm = g_tileBm[ti];
    int M = g_counts[e];
    int bn = blockIdx.x * 128;
    const __nv_bfloat16* A = g_hb + (size_t)g_off[e] * FDIM;
    const __nv_bfloat16* B = g_bwo + (size_t)e * DMODEL * FDIM;
    const float* bias = Bo + (size_t)e * DMODEL;
    GEMM_PROLOGUE();
    DENSE_AROW(A, FDIM);
    gemm_bf16_core(Ar, av, B, FDIM, bn, su, c);
    #pragma unroll
    for (int mi = 0; mi < 4; mi++)
        #pragma unroll
        for (int half = 0; half < 2; half++) {
            int row = bm + wm + (mi << 4) + g + half * 8;
            if (row >= M) continue;
            int gr = g_off[e] + row;
            float sc = g_rowScale[gr];
            #pragma unroll
            for (int ni = 0; ni < 4; ni++) {
                int col = bn + wn + (ni << 3) + 2 * tig;
                float2 v;
                v.x = sc * (c[mi][ni][half * 2]     + bias[col]);
                v.y = sc * (c[mi][ni][half * 2 + 1] + bias[col + 1]);
                *(float2*)&g_dout[(size_t)gr * DMODEL + col] = v;
            }
        }
}

__global__ __launch_bounds__(128) void moe_combine(float* __restrict__ Out)
{
    int t = blockIdx.x;
    int tid = threadIdx.x;
    int r0 = g_pairRow[t * 2];
    int r1 = g_pairRow[t * 2 + 1];
    float4 a = ((const float4*)(g_dout + (size_t)r0 * DMODEL))[tid];
    float4 b = ((const float4*)(g_dout + (size_t)r1 * DMODEL))[tid];
    float4 o = ((const float4*)(Out + (size_t)t * DMODEL))[tid];
    o.x += a.x + b.x; o.y += a.y + b.y;
    o.z += a.z + b.z; o.w += a.w + b.w;
    ((float4*)(Out + (size_t)t * DMODEL))[tid] = o;
}

// ---------------- bf16 flash attention, Bq=128, 3-stage K/V (round-12) --------
#define ATTN_STAGE_U32 (2 * 64 * 36)
#define ATTN_SMEM_BYTES ((128 * 36 + 3 * ATTN_STAGE_U32) * 4)

__global__ __launch_bounds__(128, 3) void flash_attn_bf16(
    const __nv_bfloat16* __restrict__ qkv, __nv_bfloat16* __restrict__ outb)
{
    extern __shared__ unsigned asm_[];
    unsigned (*Qu)[36] = (unsigned(*)[36])asm_;
    unsigned* kvbase = asm_ + 128 * 36;

    const int tid = threadIdx.x;
    const int w = tid >> 5, lane = tid & 31;
    const int g = lane >> 2, tig = lane & 3;
    LDSM_OFFS();
    const int h = blockIdx.y;
    const int q0 = blockIdx.x * 128;
    const int m0 = w * 32;
    const int nkt = SEQ / 64;
    const unsigned kvB = smem_u32(kvbase);

    #define KV_ISSUE(kt_, st_) do {                                              \
        int kr0_ = (kt_) << 6;                                                   \
        unsigned sb_ = kvB + (unsigned)(st_) * (ATTN_STAGE_U32 * 4);             \
        _Pragma("unroll")                                                        \
        for (int i_ = 0; i_ < 4; i_++) {                                         \
            int f_ = tid + i_ * 128;                                             \
            int col_ = f_ >> 3, ch_ = f_ & 7;                                    \
            const __nv_bfloat16* base_ =                                         \
                qkv + (size_t)(kr0_ + col_) * 1536 + 512 + h * 64 + ch_ * 8;     \
            unsigned ko_ = sb_ + (unsigned)(col_ * 36 + ch_ * 4) * 4;            \
            cpa16(ko_, base_, 16);                                               \
            cpa16(ko_ + 64 * 36 * 4, base_ + 512, 16);                           \
        }                                                                        \
        cpa_commit();                                                            \
    } while (0)

    KV_ISSUE(0, 0);
    KV_ISSUE(1, 1);

    #pragma unroll
    for (int i = 0; i < 8; i++) {
        int f = tid + i * 128;
        int rq = f >> 3, u4 = (f & 7) << 2;
        *(uint4*)&Qu[rq][u4] =
            *(const uint4*)(qkv + (size_t)(q0 + rq) * 1536 + h * 64 + (u4 << 1));
    }

    float o[2][8][4];
    #pragma unroll
    for (int mi = 0; mi < 2; mi++)
        #pragma unroll
        for (int nt = 0; nt < 8; nt++)
            #pragma unroll
            for (int j = 0; j < 4; j++) o[mi][nt][j] = 0.f;
    float mr[2][2] = {{-1e30f, -1e30f}, {-1e30f, -1e30f}};
    float lr[2][2] = {{0.f, 0.f}, {0.f, 0.f}};

    const int lt = lane >> 3, lrow = lane & 7;
    const int koff = ((lt & 1) << 3) + lrow;
    const int doff = (lt >> 1) << 2;

    int stC = 0, stI = 2;
    for (int kt = 0; kt < nkt; kt++) {
        if (kt < nkt - 1) asm volatile("cp.async.wait_group 1;\n" ::: "memory");
        else              asm volatile("cp.async.wait_group 0;\n" ::: "memory");
        __syncthreads();
        if (kt + 2 < nkt) KV_ISSUE(kt + 2, stI);
        unsigned (*Ku)[36] = (unsigned(*)[36])(kvbase + stC * ATTN_STAGE_U32);
        unsigned (*Vu)[36] = Ku + 64;

        float s[2][8][4];
        #pragma unroll
        for (int mi = 0; mi < 2; mi++)
            #pragma unroll
            for (int nt = 0; nt < 8; nt++)
                #pragma unroll
                for (int j = 0; j < 4; j++) s[mi][nt][j] = 0.f;
        #pragma unroll
        for (int ktt = 0; ktt < 4; ktt++) {
            const int kb = ktt << 3;
            unsigned a[2][4];
            #pragma unroll
            for (int mi = 0; mi < 2; mi++)
                ldsm4(a[mi][0], a[mi][1], a[mi][2], a[mi][3],
                      smem_u32(&Qu[m0 + (mi << 4) + arow_off][kb + acol_off]));
            #pragma unroll
            for (int ntp = 0; ntp < 4; ntp++) {
                unsigned b00, b01, b10, b11;
                ldsm4(b00, b01, b10, b11,
                      smem_u32(&Ku[(ntp << 4) + brow_off][kb + bcol_off]));
                mma16(s[0][2*ntp],   a[0][0], a[0][1], a[0][2], a[0][3], b00, b01);
                mma16(s[1][2*ntp],   a[1][0], a[1][1], a[1][2], a[1][3], b00, b01);
                mma16(s[0][2*ntp+1], a[0][0], a[0][1], a[0][2], a[0][3], b10, b11);
                mma16(s[1][2*ntp+1], a[1][0], a[1][1], a[1][2], a[1][3], b10, b11);
            }
        }

        #pragma unroll
        for (int mi = 0; mi < 2; mi++) {
            float mx0 = mr[mi][0], mx1 = mr[mi][1];
            #pragma unroll
            for (int nt = 0; nt < 8; nt++) {
                mx0 = fmaxf(mx0, fmaxf(s[mi][nt][0], s[mi][nt][1]));
                mx1 = fmaxf(mx1, fmaxf(s[mi][nt][2], s[mi][nt][3]));
            }
            mx0 = fmaxf(mx0, __shfl_xor_sync(0xffffffffu, mx0, 1));
            mx0 = fmaxf(mx0, __shfl_xor_sync(0xffffffffu, mx0, 2));
            mx1 = fmaxf(mx1, __shfl_xor_sync(0xffffffffu, mx1, 1));
            mx1 = fmaxf(mx1, __shfl_xor_sync(0xffffffffu, mx1, 2));
            float al0 = __expf(mr[mi][0] - mx0);
            float al1 = __expf(mr[mi][1] - mx1);
            float sum0 = 0.f, sum1 = 0.f;
            #pragma unroll
            for (int nt = 0; nt < 8; nt++) {
                s[mi][nt][0] = __expf(s[mi][nt][0] - mx0);
                s[mi][nt][1] = __expf(s[mi][nt][1] - mx0);
                s[mi][nt][2] = __expf(s[mi][nt][2] - mx1);
                s[mi][nt][3] = __expf(s[mi][nt][3] - mx1);
                sum0 += s[mi][nt][0] + s[mi][nt][1];
                sum1 += s[mi][nt][2] + s[mi][nt][3];
            }
            sum0 += __shfl_xor_sync(0xffffffffu, sum0, 1);
            sum0 += __shfl_xor_sync(0xffffffffu, sum0, 2);
            sum1 += __shfl_xor_sync(0xffffffffu, sum1, 1);
            sum1 += __shfl_xor_sync(0xffffffffu, sum1, 2);
            lr[mi][0] = lr[mi][0] * al0 + sum0; mr[mi][0] = mx0;
            lr[mi][1] = lr[mi][1] * al1 + sum1; mr[mi][1] = mx1;
            #pragma unroll
            for (int nt = 0; nt < 8; nt++) {
                o[mi][nt][0] *= al0; o[mi][nt][1] *= al0;
                o[mi][nt][2] *= al1; o[mi][nt][3] *= al1;
            }
        }

        #pragma unroll
        for (int ktt = 0; ktt < 4; ktt++) {
            unsigned a[2][4];
            #pragma unroll
            for (int mi = 0; mi < 2; mi++) {
                a[mi][0] = packbf(s[mi][2*ktt][0],   s[mi][2*ktt][1]);
                a[mi][1] = packbf(s[mi][2*ktt][2],   s[mi][2*ktt][3]);
                a[mi][2] = packbf(s[mi][2*ktt+1][0], s[mi][2*ktt+1][1]);
                a[mi][3] = packbf(s[mi][2*ktt+1][2], s[mi][2*ktt+1][3]);
            }
            const int krow = (ktt << 4) + koff;
            #pragma unroll
            for (int ntp = 0; ntp < 4; ntp++) {
                unsigned b0, b1, b2, b3;
                ldsm4t(b0, b1, b2, b3,
                       smem_u32(&Vu[krow][(ntp << 3) + doff]));
                mma16(o[0][2*ntp],   a[0][0], a[0][1], a[0][2], a[0][3], b0, b1);
                mma16(o[1][2*ntp],   a[1][0], a[1][1], a[1][2], a[1][3], b0, b1);
                mma16(o[0][2*ntp+1], a[0][0], a[0][1], a[0][2], a[0][3], b2, b3);
                mma16(o[1][2*ntp+1], a[1][0], a[1][1], a[1][2], a[1][3], b2, b3);
            }
        }
        stC = (stC == 2) ? 0 : stC + 1;
        stI = (stI == 2) ? 0 : stI + 1;
    }
    #undef KV_ISSUE

    #pragma unroll
    for (int mi = 0; mi < 2; mi++) {
        float inv0 = 1.f / lr[mi][0], inv1 = 1.f / lr[mi][1];
        int mb = m0 + (mi << 4);
        #pragma unroll
        for (int nt = 0; nt < 8; nt++) {
            int col = h * 64 + (nt << 3) + 2 * tig;
            *(unsigned*)&outb[(size_t)(q0 + mb + g) * DMODEL + col] =
                packbf(o[mi][nt][0] * inv0, o[mi][nt][1] * inv0);
            *(unsigned*)&outb[(size_t)(q0 + mb + g + 8) * DMODEL + col] =
                packbf(o[mi][nt][2] * inv1, o[mi][nt][3] * inv1);
        }
    }
}

// ---------------- gating (fp32 path: routing must match reference) ------------
__global__ __launch_bounds__(128) void gate_topk(
    const float* __restrict__ xn, const float* __restrict__ gw,
    const float* __restrict__ gb)
{
    int warp = threadIdx.x >> 5;
    int lane = threadIdx.x & 31;
    int t = blockIdx.x * 4 + warp;
    float acc[NEXP];
    #pragma unroll
    for (int e = 0; e < NEXP; e++) acc[e] = 0.f;
    for (int d = lane; d < DMODEL; d += 32) {
        float xv = xn[(size_t)t * DMODEL + d];
        #pragma unroll
        for (int e = 0; e < NEXP; e++) acc[e] = fmaf(xv, gw[e * DMODEL + d], acc[e]);
    }
    #pragma unroll
    for (int e = 0; e < NEXP; e++)
        #pragma unroll
        for (int o = 16; o > 0; o >>= 1)
            acc[e] += __shfl_xor_sync(0xffffffffu, acc[e], o);
    if (lane == 0) {
        float lg[NEXP];
        float mx = -1e30f;
        #pragma unroll
        for (int e = 0; e < NEXP; e++) { lg[e] = acc[e] + gb[e]; mx = fmaxf(mx, lg[e]); }
        float sum = 0.f;
        #pragma unroll
        for (int e = 0; e < NEXP; e++) { lg[e] = __expf(lg[e] - mx); sum += lg[e]; }
        float inv = 1.f / sum;
        int e0 = 0; float p0 = lg[0];
        #pragma unroll
        for (int e = 1; e < NEXP; e++) if (lg[e] > p0) { p0 = lg[e]; e0 = e; }
        int e1 = -1; float p1 = -1.f;
        #pragma unroll
        for (int e = 0; e < NEXP; e++)
            if (e != e0 && lg[e] > p1) { p1 = lg[e]; e1 = e; }
        g_tidx[t * 2] = e0;         g_tidx[t * 2 + 1] = e1;
        g_tscale[t * 2] = p0 * inv; g_tscale[t * 2 + 1] = p1 * inv;
        atomicAdd(&g_counts[e0], 1);
        atomicAdd(&g_counts[e1], 1);
    }
}

__global__ void zero_counts_k() {
    if (threadIdx.x < NEXP) { g_counts[threadIdx.x] = 0; g_cursor[threadIdx.x] = 0; }
}

__global__ void calc_offsets_k() {
    int o = 0, nt = 0;
    for (int e = 0; e < NEXP; e++) {
        g_off[e] = o;
        o += g_counts[e];
    }
    for (int e = 0; e < NEXP; e++)
        for (int bm = 0; bm < g_counts[e]; bm += 128) {
            g_tileE[nt] = e;
            g_tileBm[nt] = bm;
            nt++;
        }
    g_ntiles = nt;
}

__global__ __launch_bounds__(256) void assign_rows()
{
    int p = blockIdx.x * 256 + threadIdx.x;
    if (p >= NPAIR) return;
    int e = g_tidx[p];
    int pos = g_off[e] + atomicAdd(&g_cursor[e], 1);
    g_rowTok[pos] = p >> 1;
    g_rowScale[pos] = g_tscale[p];
    g_pairRow[p] = pos;
}

// ---------------- launch -----------------------------------------------------
extern "C" void kernel_launch(void* const* d_in, const int* in_sizes, int n_in,
                              void* d_out, int out_size)
{
    const float* src        = (const float*)d_in[0];
    const float* in_proj_w  = (const float*)d_in[1];
    const float* in_proj_b  = (const float*)d_in[2];
    const float* out_proj_w = (const float*)d_in[3];
    const float* out_proj_b = (const float*)d_in[4];
    const float* ln1_g      = (const float*)d_in[5];
    const float* ln1_b      = (const float*)d_in[6];
    const float* ln2_g      = (const float*)d_in[7];
    const float* ln2_b      = (const float*)d_in[8];
    const float* gate_w     = (const float*)d_in[9];
    const float* gate_b     = (const float*)d_in[10];
    const float* w1         = (const float*)d_in[11];
    const float* b1         = (const float*)d_in[12];
    const float* w2         = (const float*)d_in[13];
    const float* b2         = (const float*)d_in[14];
    const float* wo         = (const float*)d_in[15];
    const float* bo         = (const float*)d_in[16];
    float* out = (float*)d_out;

    float *xn;
    __nv_bfloat16 *xnb, *qkvb, *attnb, *bwin, *bwout;
    cudaGetSymbolAddress((void**)&xn,    g_xn);
    cudaGetSymbolAddress((void**)&xnb,   g_xnb);
    cudaGetSymbolAddress((void**)&qkvb,  g_qkvb);
    cudaGetSymbolAddress((void**)&attnb, g_attnb);
    cudaGetSymbolAddress((void**)&bwin,  g_bwin);
    cudaGetSymbolAddress((void**)&bwout, g_bwout);

    cudaFuncSetAttribute(flash_attn_bf16,
                         cudaFuncAttributeMaxDynamicSharedMemorySize,
                         ATTN_SMEM_BYTES);
    cudaFuncSetAttribute(gemm_bf16_nt,
                         cudaFuncAttributeMaxDynamicSharedMemorySize, GEMM_SMEM_BYTES);
    cudaFuncSetAttribute(gemm_qkv,
                         cudaFuncAttributeMaxDynamicSharedMemorySize, GEMM_SMEM_BYTES);
    cudaFuncSetAttribute(moe_up1,
                         cudaFuncAttributeMaxDynamicSharedMemorySize, GEMM_SMEM_BYTES);
    cudaFuncSetAttribute(moe_up2,
                         cudaFuncAttributeMaxDynamicSharedMemorySize, GEMM_SMEM_BYTES);
    cudaFuncSetAttribute(moe_down,
                         cudaFuncAttributeMaxDynamicSharedMemorySize, GEMM_SMEM_BYTES);

    f2bf_all<<<3200, 256>>>(in_proj_w, out_proj_w, w1, w2, wo);

    zero_counts_k<<<1, 32>>>();

    // ---- attention block ----
    layernorm_k<<<SEQ, 128>>>(src, ln1_g, ln1_b, xn, xnb);
    gemm_qkv<<<dim3(12, 32), 256, GEMM_SMEM_BYTES>>>(xnb, bwin, in_proj_b, qkvb,
                                                     SEQ, 3 * DMODEL, DMODEL);
    flash_attn_bf16<<<dim3(SEQ / 128, NHEAD), 128, ATTN_SMEM_BYTES>>>(qkvb, attnb);
    gemm_bf16_nt<<<dim3(4, 32), 256, GEMM_SMEM_BYTES>>>(attnb, bwout, out_proj_b,
                                                        src, out, SEQ, DMODEL, DMODEL);

    // ---- MoE block ----
    layernorm_k<<<SEQ, 128>>>(out, ln2_g, ln2_b, xn, xnb);
    gate_topk<<<SEQ / 4, 128>>>(xn, gate_w, gate_b);
    calc_offsets_k<<<1, 1>>>();
    assign_rows<<<NPAIR / 256, 256>>>();
    moe_up1<<<dim3(FDIM / 128, MAXTILE - 8), 256, GEMM_SMEM_BYTES>>>(b1);
    moe_up2<<<dim3(FDIM / 128, MAXTILE - 8), 256, GEMM_SMEM_BYTES>>>(b2);
    moe_down<<<dim3(DMODEL / 128, MAXTILE - 8), 256, GEMM_SMEM_BYTES>>>(bo);
    moe_combine<<<SEQ, 128>>>(out);
}

// round 16
// speedup vs baseline: 1.0537x; 1.0537x over previous
#include <cuda_runtime.h>
#include <cuda_bf16.h>
#include <math.h>

#define SEQ 4096
#define DMODEL 512
#define NHEAD 8
#define FDIM 2048
#define NEXP 8
#define NPAIR (SEQ * 2)
#define MAXTILE 80

// ---------------- scratch (device globals; no allocations allowed) ----------
__device__ float g_xn[SEQ * DMODEL];
__device__ __nv_bfloat16 g_xnb[SEQ * DMODEL];
__device__ __nv_bfloat16 g_qkvb[SEQ * 3 * DMODEL];
__device__ __nv_bfloat16 g_attnb[SEQ * DMODEL];
__device__ __nv_bfloat16 g_h1b[NPAIR * FDIM];
__device__ __nv_bfloat16 g_hb[NPAIR * FDIM];
__device__ float g_dout[NPAIR * DMODEL];
__device__ __nv_bfloat16 g_bwin[3 * DMODEL * DMODEL];
__device__ __nv_bfloat16 g_bwout[DMODEL * DMODEL];
__device__ __nv_bfloat16 g_bw1[NEXP * FDIM * DMODEL];
__device__ __nv_bfloat16 g_bw2[NEXP * FDIM * DMODEL];
__device__ __nv_bfloat16 g_bwo[NEXP * DMODEL * FDIM];
__device__ int   g_tidx[NPAIR];
__device__ float g_tscale[NPAIR];
__device__ int   g_counts[NEXP];
__device__ int   g_cursor[NEXP];
__device__ int   g_off[NEXP];
__device__ float g_rowScale[NPAIR];
__device__ int   g_rowTok[NPAIR];
__device__ int   g_pairRow[NPAIR];
__device__ int   g_tileE[MAXTILE];
__device__ int   g_tileBm[MAXTILE];
__device__ int   g_ntiles;
__device__ int   g_gateDone;

// ---------------- helpers -----------------------------------------------------
__device__ __forceinline__ void mma16(float c[4],
    unsigned a0, unsigned a1, unsigned a2, unsigned a3,
    unsigned b0, unsigned b1)
{
    asm volatile(
        "mma.sync.aligned.m16n8k16.row.col.f32.bf16.bf16.f32 "
        "{%0,%1,%2,%3}, {%4,%5,%6,%7}, {%8,%9}, {%0,%1,%2,%3};\n"
        : "+f"(c[0]), "+f"(c[1]), "+f"(c[2]), "+f"(c[3])
        : "r"(a0), "r"(a1), "r"(a2), "r"(a3), "r"(b0), "r"(b1));
}

__device__ __forceinline__ void ldsm4(unsigned& r0, unsigned& r1,
                                      unsigned& r2, unsigned& r3, unsigned addr)
{
    asm volatile(
        "ldmatrix.sync.aligned.m8n8.x4.shared.b16 {%0,%1,%2,%3}, [%4];\n"
        : "=r"(r0), "=r"(r1), "=r"(r2), "=r"(r3) : "r"(addr));
}

__device__ __forceinline__ void ldsm4t(unsigned& r0, unsigned& r1,
                                       unsigned& r2, unsigned& r3, unsigned addr)
{
    asm volatile(
        "ldmatrix.sync.aligned.m8n8.x4.trans.shared.b16 {%0,%1,%2,%3}, [%4];\n"
        : "=r"(r0), "=r"(r1), "=r"(r2), "=r"(r3) : "r"(addr));
}

__device__ __forceinline__ unsigned smem_u32(const void* p) {
    return (unsigned)__cvta_generic_to_shared(p);
}
__device__ __forceinline__ void cpa16(unsigned dst, const void* src, int vbytes) {
    asm volatile("cp.async.cg.shared.global [%0], [%1], 16, %2;\n"
                 :: "r"(dst), "l"(src), "r"(vbytes) : "memory");
}
__device__ __forceinline__ void cpa_commit() {
    asm volatile("cp.async.commit_group;\n" ::: "memory");
}
__device__ __forceinline__ unsigned packbf(float a, float b) {
    __nv_bfloat162 p = __floats2bfloat162_rn(a, b);
    return *(unsigned*)&p;
}

#define LDSM_OFFS() \
    const int rl_ = lane & 7, quad_ = lane >> 3; \
    const int arow_off = rl_ + ((quad_ & 1) << 3); \
    const int acol_off = (quad_ >> 1) << 2; \
    const int brow_off = rl_ + ((quad_ >> 1) << 3); \
    const int bcol_off = (quad_ & 1) << 2;

// ---------------- fused fp32 -> bf16 convert + counter init -------------------
// block = 2048 float4. Regions (blocks): bwin[0,96) bwout[96,128)
// w1[128,1152) w2[1152,2176) wo[2176,3200).
__global__ __launch_bounds__(256) void f2bf_all(
    const float* __restrict__ w_in, const float* __restrict__ w_out,
    const float* __restrict__ w1, const float* __restrict__ w2,
    const float* __restrict__ wo)
{
    if (blockIdx.x == 0 && threadIdx.x < NEXP + 1) {
        if (threadIdx.x < NEXP) {
            g_counts[threadIdx.x] = 0;
            g_cursor[threadIdx.x] = 0;
        } else {
            g_gateDone = 0;
        }
    }
    int blk = blockIdx.x;
    const float4* src;
    uint2* dst;
    size_t base;
    if (blk < 96)        { src = (const float4*)w_in;  dst = (uint2*)g_bwin;  base = (size_t)blk * 2048; }
    else if (blk < 128)  { src = (const float4*)w_out; dst = (uint2*)g_bwout; base = (size_t)(blk - 96) * 2048; }
    else if (blk < 1152) { src = (const float4*)w1;    dst = (uint2*)g_bw1;   base = (size_t)(blk - 128) * 2048; }
    else if (blk < 2176) { src = (const float4*)w2;    dst = (uint2*)g_bw2;   base = (size_t)(blk - 1152) * 2048; }
    else                 { src = (const float4*)wo;    dst = (uint2*)g_bwo;   base = (size_t)(blk - 2176) * 2048; }
    size_t i0 = base + threadIdx.x;
    float4 v[8];
    #pragma unroll
    for (int j = 0; j < 8; j++) v[j] = src[i0 + j * 256];
    #pragma unroll
    for (int j = 0; j < 8; j++) {
        uint2 u; u.x = packbf(v[j].x, v[j].y); u.y = packbf(v[j].z, v[j].w);
        dst[i0 + j * 256] = u;
    }
}

// ---------------- layernorm (dual fp32 + bf16 output) -------------------------
__global__ __launch_bounds__(128) void layernorm_k(
    const float* __restrict__ x, const float* __restrict__ g,
    const float* __restrict__ b, float* __restrict__ y,
    __nv_bfloat16* __restrict__ yb)
{
    int t = blockIdx.x;
    int tid = threadIdx.x;
    float4 v = ((const float4*)(x + (size_t)t * DMODEL))[tid];
    float s  = v.x + v.y + v.z + v.w;
    float ss = v.x * v.x + v.y * v.y + v.z * v.z + v.w * v.w;
    #pragma unroll
    for (int o = 16; o > 0; o >>= 1) {
        s  += __shfl_xor_sync(0xffffffffu, s, o);
        ss += __shfl_xor_sync(0xffffffffu, ss, o);
    }
    __shared__ float sw[4], ssw[4];
    __shared__ float meanS, rstdS;
    int lane = tid & 31, w = tid >> 5;
    if (lane == 0) { sw[w] = s; ssw[w] = ss; }
    __syncthreads();
    if (tid == 0) {
        float S = sw[0] + sw[1] + sw[2] + sw[3];
        float SS = ssw[0] + ssw[1] + ssw[2] + ssw[3];
        float mean = S / (float)DMODEL;
        float var = SS / (float)DMODEL - mean * mean;
        meanS = mean;
        rstdS = rsqrtf(var + 1e-5f);
    }
    __syncthreads();
    float mean = meanS, rstd = rstdS;
    float4 gg = ((const float4*)g)[tid];
    float4 bb = ((const float4*)b)[tid];
    float4 o;
    o.x = (v.x - mean) * rstd * gg.x + bb.x;
    o.y = (v.y - mean) * rstd * gg.y + bb.y;
    o.z = (v.z - mean) * rstd * gg.z + bb.z;
    o.w = (v.w - mean) * rstd * gg.w + bb.w;
    ((float4*)(y + (size_t)t * DMODEL))[tid] = o;
    uint2 u; u.x = packbf(o.x, o.y); u.y = packbf(o.z, o.w);
    ((uint2*)(yb + (size_t)t * DMODEL))[tid] = u;
}

// ---------------- bf16 GEMM core: 3-stage cp.async, BK=32 (round-12 best) -----
// BM=BN=128, 256 threads (8 warps 2x4), warp tile 64x32, m16n8k16.
// Stage = A(10240B) + B(10240B) = 20480B; 3 stages = 60KB dynamic smem.
#define GEMM_SMEM_BYTES (3 * 20480)

__device__ __forceinline__ void gemm_bf16_core(
    const __nv_bfloat16* __restrict__ Ar, int av,
    const __nv_bfloat16* __restrict__ B,
    int K, int bn, unsigned* su, float c[4][4][4])
{
    const int tid = threadIdx.x;
    const int lane = tid & 31;
    const int w = tid >> 5, wm = (w >> 2) << 6, wn = (w & 3) << 5;
    LDSM_OFFS();
    const int r = tid >> 1;
    const int seg0 = (tid & 1) << 1;
    const int nk = K >> 5;
    const __nv_bfloat16* Br = B + (size_t)(bn + r) * K;
    const unsigned suB = smem_u32(su);
    const unsigned dstA0 = suB + (unsigned)(r * 20) * 4;

    #define GEMM_ISSUE(kt_, st_) do {                                        \
        int k0_ = (kt_) << 5;                                                \
        unsigned sb_ = (unsigned)(st_) * 20480u;                             \
        _Pragma("unroll")                                                    \
        for (int i_ = 0; i_ < 2; i_++) {                                     \
            int seg_ = seg0 + i_;                                            \
            cpa16(dstA0 + sb_ + seg_ * 16, Ar + k0_ + seg_ * 8, av);         \
            cpa16(dstA0 + sb_ + 10240 + seg_ * 16, Br + k0_ + seg_ * 8, 16); \
        }                                                                    \
        cpa_commit();                                                        \
    } while (0)

    GEMM_ISSUE(0, 0);
    GEMM_ISSUE(1, 1);

    int stC = 0, stI = 2;
    for (int kt = 0; kt < nk; kt++) {
        if (kt < nk - 1) asm volatile("cp.async.wait_group 1;\n" ::: "memory");
        else             asm volatile("cp.async.wait_group 0;\n" ::: "memory");
        __syncthreads();          // all warps done with stage stI's old chunk
        if (kt + 2 < nk) GEMM_ISSUE(kt + 2, stI);
        const unsigned stageA = suB + (unsigned)stC * 20480u;
        const unsigned stageB = stageA + 10240u;
        #pragma unroll
        for (int kk = 0; kk < 2; kk++) {
            const int kb = kk << 3;
            unsigned a[4][4], b[4][2];
            const unsigned aAddr =
                stageA + (unsigned)((wm + arow_off) * 20 + kb + acol_off) * 4;
            #pragma unroll
            for (int mi = 0; mi < 4; mi++)
                ldsm4(a[mi][0], a[mi][1], a[mi][2], a[mi][3],
                      aAddr + (unsigned)(mi * 16 * 20) * 4);
            const unsigned bAddr =
                stageB + (unsigned)((wn + brow_off) * 20 + kb + bcol_off) * 4;
            ldsm4(b[0][0], b[0][1], b[1][0], b[1][1], bAddr);
            ldsm4(b[2][0], b[2][1], b[3][0], b[3][1],
                  bAddr + (unsigned)(16 * 20) * 4);
            #pragma unroll
            for (int mi = 0; mi < 4; mi++)
                #pragma unroll
                for (int ni = 0; ni < 4; ni++)
                    mma16(c[mi][ni], a[mi][0], a[mi][1], a[mi][2], a[mi][3],
                          b[ni][0], b[ni][1]);
        }
        stC = (stC == 2) ? 0 : stC + 1;
        stI = (stI == 2) ? 0 : stI + 1;
    }
    #undef GEMM_ISSUE
}

#define GEMM_PROLOGUE() \
    extern __shared__ unsigned su[]; \
    float c[4][4][4]; \
    _Pragma("unroll") \
    for (int mi = 0; mi < 4; mi++) \
        _Pragma("unroll") \
        for (int ni = 0; ni < 4; ni++) \
            _Pragma("unroll") \
            for (int j = 0; j < 4; j++) c[mi][ni][j] = 0.f; \
    const int lane = threadIdx.x & 31; \
    const int g = lane >> 2, tig = lane & 3; \
    const int w = threadIdx.x >> 5; \
    const int wm = (w >> 2) << 6, wn = (w & 3) << 5;

#define DENSE_AROW(Abase, Kd) \
    const int r_ = threadIdx.x >> 1; \
    const int arow_ = (bm + r_ < M) ? (bm + r_) : 0; \
    const int av = (bm + r_ < M) ? 16 : 0; \
    const __nv_bfloat16* Ar = (Abase) + (size_t)arow_ * (Kd);

__global__ __launch_bounds__(256, 2) void gemm_bf16_nt(
    const __nv_bfloat16* __restrict__ A, const __nv_bfloat16* __restrict__ B,
    const float* __restrict__ bias, const float* __restrict__ resid,
    float* __restrict__ C, int M, int N, int K)
{
    const int bm = blockIdx.y * 128;
    const int bn = blockIdx.x * 128;
    GEMM_PROLOGUE();
    DENSE_AROW(A, K);
    gemm_bf16_core(Ar, av, B, K, bn, su, c);
    #pragma unroll
    for (int mi = 0; mi < 4; mi++)
        #pragma unroll
        for (int half = 0; half < 2; half++) {
            int row = bm + wm + (mi << 4) + g + half * 8;
            if (row >= M) continue;
            #pragma unroll
            for (int ni = 0; ni < 4; ni++) {
                int col = bn + wn + (ni << 3) + 2 * tig;
                float v0 = c[mi][ni][half * 2]     + bias[col];
                float v1 = c[mi][ni][half * 2 + 1] + bias[col + 1];
                if (resid) {
                    v0 += resid[(size_t)row * N + col];
                    v1 += resid[(size_t)row * N + col + 1];
                }
                float2 v; v.x = v0; v.y = v1;
                *(float2*)&C[(size_t)row * N + col] = v;
            }
        }
}

__global__ __launch_bounds__(256, 2) void gemm_qkv(
    const __nv_bfloat16* __restrict__ A, const __nv_bfloat16* __restrict__ B,
    const float* __restrict__ bias, __nv_bfloat16* __restrict__ C,
    int M, int N, int K)
{
    const int bm = blockIdx.y * 128;
    const int bn = blockIdx.x * 128;
    GEMM_PROLOGUE();
    DENSE_AROW(A, K);
    gemm_bf16_core(Ar, av, B, K, bn, su, c);
    #pragma unroll
    for (int mi = 0; mi < 4; mi++)
        #pragma unroll
        for (int half = 0; half < 2; half++) {
            int row = bm + wm + (mi << 4) + g + half * 8;
            #pragma unroll
            for (int ni = 0; ni < 4; ni++) {
                int col = bn + wn + (ni << 3) + 2 * tig;
                float sc = (col < DMODEL) ? 0.125f : 1.f;
                float v0 = (c[mi][ni][half * 2]     + bias[col]) * sc;
                float v1 = (c[mi][ni][half * 2 + 1] + bias[col + 1]) * sc;
                *(unsigned*)&C[(size_t)row * N + col] = packbf(v0, v1);
            }
        }
}

#define MOE_AROW() \
    const int r_ = threadIdx.x >> 1; \
    const bool vld_ = (bm + r_ < M); \
    const int tok_ = vld_ ? g_rowTok[g_off[e] + bm + r_] : 0; \
    const int av = vld_ ? 16 : 0; \
    const __nv_bfloat16* Ar = g_xnb + (size_t)tok_ * DMODEL;

__global__ __launch_bounds__(256, 2) void moe_up1(const float* __restrict__ Ball)
{
    int ti = blockIdx.y;
    if (ti >= g_ntiles) return;
    int e = g_tileE[ti];
    int bm = g_tileBm[ti];
    int M = g_counts[e];
    int bn = blockIdx.x * 128;
    const __nv_bfloat16* B = g_bw1 + (size_t)e * FDIM * DMODEL;
    const float* bias = Ball + (size_t)e * FDIM;
    __nv_bfloat16* C = g_h1b + (size_t)g_off[e] * FDIM;
    GEMM_PROLOGUE();
    MOE_AROW();
    gemm_bf16_core(Ar, av, B, DMODEL, bn, su, c);
    #pragma unroll
    for (int mi = 0; mi < 4; mi++)
        #pragma unroll
        for (int half = 0; half < 2; half++) {
            int row = bm + wm + (mi << 4) + g + half * 8;
            if (row >= M) continue;
            #pragma unroll
            for (int ni = 0; ni < 4; ni++) {
                int col = bn + wn + (ni << 3) + 2 * tig;
                *(unsigned*)&C[(size_t)row * FDIM + col] =
                    packbf(c[mi][ni][half * 2]     + bias[col],
                           c[mi][ni][half * 2 + 1] + bias[col + 1]);
            }
        }
}

__global__ __launch_bounds__(256, 2) void moe_up2(const float* __restrict__ Ball)
{
    int ti = blockIdx.y;
    if (ti >= g_ntiles) return;
    int e = g_tileE[ti];
    int bm = g_tileBm[ti];
    int M = g_counts[e];
    int bn = blockIdx.x * 128;
    const __nv_bfloat16* B = g_bw2 + (size_t)e * FDIM * DMODEL;
    const float* bias = Ball + (size_t)e * FDIM;
    const __nv_bfloat16* H1 = g_h1b + (size_t)g_off[e] * FDIM;
    __nv_bfloat16* HB = g_hb + (size_t)g_off[e] * FDIM;
    GEMM_PROLOGUE();
    MOE_AROW();
    gemm_bf16_core(Ar, av, B, DMODEL, bn, su, c);
    #pragma unroll
    for (int mi = 0; mi < 4; mi++)
        #pragma unroll
        for (int half = 0; half < 2; half++) {
            int row = bm + wm + (mi << 4) + g + half * 8;
            if (row >= M) continue;
            #pragma unroll
            for (int ni = 0; ni < 4; ni++) {
                int col = bn + wn + (ni << 3) + 2 * tig;
                unsigned hv = *(const unsigned*)&H1[(size_t)row * FDIM + col];
                __nv_bfloat162 hb2 = *(__nv_bfloat162*)&hv;
                float gx = __bfloat162float(hb2.x);
                float gy = __bfloat162float(hb2.y);
                float h2v0 = c[mi][ni][half * 2]     + bias[col];
                float h2v1 = c[mi][ni][half * 2 + 1] + bias[col + 1];
                float s0 = gx / (1.f + __expf(-gx));
                float s1 = gy / (1.f + __expf(-gy));
                *(unsigned*)&HB[(size_t)row * FDIM + col] = packbf(s0 * h2v0, s1 * h2v1);
            }
        }
}

__global__ __launch_bounds__(256, 2) void moe_down(const float* __restrict__ Bo)
{
    int ti = blockIdx.y;
    if (ti >= g_ntiles) return;
    int e = g_tileE[ti];
    int bm = g_tileBm[ti];
    int M = g_counts[e];
    int bn = blockIdx.x * 128;
    const __nv_bfloat16* A = g_hb + (size_t)g_off[e] * FDIM;
    const __nv_bfloat16* B = g_bwo + (size_t)e * DMODEL * FDIM;
    const float* bias = Bo + (size_t)e * DMODEL;
    GEMM_PROLOGUE();
    DENSE_AROW(A, FDIM);
    gemm_bf16_core(Ar, av, B, FDIM, bn, su, c);
    #pragma unroll
    for (int mi = 0; mi < 4; mi++)
        #pragma unroll
        for (int half = 0; half < 2; half++) {
            int row = bm + wm + (mi << 4) + g + half * 8;
            if (row >= M) continue;
            int gr = g_off[e] + row;
            float sc = g_rowScale[gr];
            #pragma unroll
            for (int ni = 0; ni < 4; ni++) {
                int col = bn + wn + (ni << 3) + 2 * tig;
                float2 v;
                v.x = sc * (c[mi][ni][half * 2]     + bias[col]);
                v.y = sc * (c[mi][ni][half * 2 + 1] + bias[col + 1]);
                *(float2*)&g_dout[(size_t)gr * DMODEL + col] = v;
            }
        }
}

__global__ __launch_bounds__(128) void moe_combine(float* __restrict__ Out)
{
    int t = blockIdx.x;
    int tid = threadIdx.x;
    int r0 = g_pairRow[t * 2];
    int r1 = g_pairRow[t * 2 + 1];
    float4 a = ((const float4*)(g_dout + (size_t)r0 * DMODEL))[tid];
    float4 b = ((const float4*)(g_dout + (size_t)r1 * DMODEL))[tid];
    float4 o = ((const float4*)(Out + (size_t)t * DMODEL))[tid];
    o.x += a.x + b.x; o.y += a.y + b.y;
    o.z += a.z + b.z; o.w += a.w + b.w;
    ((float4*)(Out + (size_t)t * DMODEL))[tid] = o;
}

// ---------------- bf16 flash attention, Bq=128, 3-stage K/V (round-12) --------
#define ATTN_STAGE_U32 (2 * 64 * 36)
#define ATTN_SMEM_BYTES ((128 * 36 + 3 * ATTN_STAGE_U32) * 4)

__global__ __launch_bounds__(128, 3) void flash_attn_bf16(
    const __nv_bfloat16* __restrict__ qkv, __nv_bfloat16* __restrict__ outb)
{
    extern __shared__ unsigned asm_[];
    unsigned (*Qu)[36] = (unsigned(*)[36])asm_;
    unsigned* kvbase = asm_ + 128 * 36;

    const int tid = threadIdx.x;
    const int w = tid >> 5, lane = tid & 31;
    const int g = lane >> 2, tig = lane & 3;
    LDSM_OFFS();
    const int h = blockIdx.y;
    const int q0 = blockIdx.x * 128;
    const int m0 = w * 32;
    const int nkt = SEQ / 64;
    const unsigned kvB = smem_u32(kvbase);

    #define KV_ISSUE(kt_, st_) do {                                              \
        int kr0_ = (kt_) << 6;                                                   \
        unsigned sb_ = kvB + (unsigned)(st_) * (ATTN_STAGE_U32 * 4);             \
        _Pragma("unroll")                                                        \
        for (int i_ = 0; i_ < 4; i_++) {                                         \
            int f_ = tid + i_ * 128;                                             \
            int col_ = f_ >> 3, ch_ = f_ & 7;                                    \
            const __nv_bfloat16* base_ =                                         \
                qkv + (size_t)(kr0_ + col_) * 1536 + 512 + h * 64 + ch_ * 8;     \
            unsigned ko_ = sb_ + (unsigned)(col_ * 36 + ch_ * 4) * 4;            \
            cpa16(ko_, base_, 16);                                               \
            cpa16(ko_ + 64 * 36 * 4, base_ + 512, 16);                           \
        }                                                                        \
        cpa_commit();                                                            \
    } while (0)

    KV_ISSUE(0, 0);
    KV_ISSUE(1, 1);

    #pragma unroll
    for (int i = 0; i < 8; i++) {
        int f = tid + i * 128;
        int rq = f >> 3, u4 = (f & 7) << 2;
        *(uint4*)&Qu[rq][u4] =
            *(const uint4*)(qkv + (size_t)(q0 + rq) * 1536 + h * 64 + (u4 << 1));
    }

    float o[2][8][4];
    #pragma unroll
    for (int mi = 0; mi < 2; mi++)
        #pragma unroll
        for (int nt = 0; nt < 8; nt++)
            #pragma unroll
            for (int j = 0; j < 4; j++) o[mi][nt][j] = 0.f;
    float mr[2][2] = {{-1e30f, -1e30f}, {-1e30f, -1e30f}};
    float lr[2][2] = {{0.f, 0.f}, {0.f, 0.f}};

    const int lt = lane >> 3, lrow = lane & 7;
    const int koff = ((lt & 1) << 3) + lrow;
    const int doff = (lt >> 1) << 2;

    int stC = 0, stI = 2;
    for (int kt = 0; kt < nkt; kt++) {
        if (kt < nkt - 1) asm volatile("cp.async.wait_group 1;\n" ::: "memory");
        else              asm volatile("cp.async.wait_group 0;\n" ::: "memory");
        __syncthreads();
        if (kt + 2 < nkt) KV_ISSUE(kt + 2, stI);
        unsigned (*Ku)[36] = (unsigned(*)[36])(kvbase + stC * ATTN_STAGE_U32);
        unsigned (*Vu)[36] = Ku + 64;

        float s[2][8][4];
        #pragma unroll
        for (int mi = 0; mi < 2; mi++)
            #pragma unroll
            for (int nt = 0; nt < 8; nt++)
                #pragma unroll
                for (int j = 0; j < 4; j++) s[mi][nt][j] = 0.f;
        #pragma unroll
        for (int ktt = 0; ktt < 4; ktt++) {
            const int kb = ktt << 3;
            unsigned a[2][4];
            #pragma unroll
            for (int mi = 0; mi < 2; mi++)
                ldsm4(a[mi][0], a[mi][1], a[mi][2], a[mi][3],
                      smem_u32(&Qu[m0 + (mi << 4) + arow_off][kb + acol_off]));
            #pragma unroll
            for (int ntp = 0; ntp < 4; ntp++) {
                unsigned b00, b01, b10, b11;
                ldsm4(b00, b01, b10, b11,
                      smem_u32(&Ku[(ntp << 4) + brow_off][kb + bcol_off]));
                mma16(s[0][2*ntp],   a[0][0], a[0][1], a[0][2], a[0][3], b00, b01);
                mma16(s[1][2*ntp],   a[1][0], a[1][1], a[1][2], a[1][3], b00, b01);
                mma16(s[0][2*ntp+1], a[0][0], a[0][1], a[0][2], a[0][3], b10, b11);
                mma16(s[1][2*ntp+1], a[1][0], a[1][1], a[1][2], a[1][3], b10, b11);
            }
        }

        #pragma unroll
        for (int mi = 0; mi < 2; mi++) {
            float mx0 = mr[mi][0], mx1 = mr[mi][1];
            #pragma unroll
            for (int nt = 0; nt < 8; nt++) {
                mx0 = fmaxf(mx0, fmaxf(s[mi][nt][0], s[mi][nt][1]));
                mx1 = fmaxf(mx1, fmaxf(s[mi][nt][2], s[mi][nt][3]));
            }
            mx0 = fmaxf(mx0, __shfl_xor_sync(0xffffffffu, mx0, 1));
            mx0 = fmaxf(mx0, __shfl_xor_sync(0xffffffffu, mx0, 2));
            mx1 = fmaxf(mx1, __shfl_xor_sync(0xffffffffu, mx1, 1));
            mx1 = fmaxf(mx1, __shfl_xor_sync(0xffffffffu, mx1, 2));
            float al0 = __expf(mr[mi][0] - mx0);
            float al1 = __expf(mr[mi][1] - mx1);
            float sum0 = 0.f, sum1 = 0.f;
            #pragma unroll
            for (int nt = 0; nt < 8; nt++) {
                s[mi][nt][0] = __expf(s[mi][nt][0] - mx0);
                s[mi][nt][1] = __expf(s[mi][nt][1] - mx0);
                s[mi][nt][2] = __expf(s[mi][nt][2] - mx1);
                s[mi][nt][3] = __expf(s[mi][nt][3] - mx1);
                sum0 += s[mi][nt][0] + s[mi][nt][1];
                sum1 += s[mi][nt][2] + s[mi][nt][3];
            }
            sum0 += __shfl_xor_sync(0xffffffffu, sum0, 1);
            sum0 += __shfl_xor_sync(0xffffffffu, sum0, 2);
            sum1 += __shfl_xor_sync(0xffffffffu, sum1, 1);
            sum1 += __shfl_xor_sync(0xffffffffu, sum1, 2);
            lr[mi][0] = lr[mi][0] * al0 + sum0; mr[mi][0] = mx0;
            lr[mi][1] = lr[mi][1] * al1 + sum1; mr[mi][1] = mx1;
            #pragma unroll
            for (int nt = 0; nt < 8; nt++) {
                o[mi][nt][0] *= al0; o[mi][nt][1] *= al0;
                o[mi][nt][2] *= al1; o[mi][nt][3] *= al1;
            }
        }

        #pragma unroll
        for (int ktt = 0; ktt < 4; ktt++) {
            unsigned a[2][4];
            #pragma unroll
            for (int mi = 0; mi < 2; mi++) {
                a[mi][0] = packbf(s[mi][2*ktt][0],   s[mi][2*ktt][1]);
                a[mi][1] = packbf(s[mi][2*ktt][2],   s[mi][2*ktt][3]);
                a[mi][2] = packbf(s[mi][2*ktt+1][0], s[mi][2*ktt+1][1]);
                a[mi][3] = packbf(s[mi][2*ktt+1][2], s[mi][2*ktt+1][3]);
            }
            const int krow = (ktt << 4) + koff;
            #pragma unroll
            for (int ntp = 0; ntp < 4; ntp++) {
                unsigned b0, b1, b2, b3;
                ldsm4t(b0, b1, b2, b3,
                       smem_u32(&Vu[krow][(ntp << 3) + doff]));
                mma16(o[0][2*ntp],   a[0][0], a[0][1], a[0][2], a[0][3], b0, b1);
                mma16(o[1][2*ntp],   a[1][0], a[1][1], a[1][2], a[1][3], b0, b1);
                mma16(o[0][2*ntp+1], a[0][0], a[0][1], a[0][2], a[0][3], b2, b3);
                mma16(o[1][2*ntp+1], a[1][0], a[1][1], a[1][2], a[1][3], b2, b3);
            }
        }
        stC = (stC == 2) ? 0 : stC + 1;
        stI = (stI == 2) ? 0 : stI + 1;
    }
    #undef KV_ISSUE

    #pragma unroll
    for (int mi = 0; mi < 2; mi++) {
        float inv0 = 1.f / lr[mi][0], inv1 = 1.f / lr[mi][1];
        int mb = m0 + (mi << 4);
        #pragma unroll
        for (int nt = 0; nt < 8; nt++) {
            int col = h * 64 + (nt << 3) + 2 * tig;
            *(unsigned*)&outb[(size_t)(q0 + mb + g) * DMODEL + col] =
                packbf(o[mi][nt][0] * inv0, o[mi][nt][1] * inv0);
            *(unsigned*)&outb[(size_t)(q0 + mb + g + 8) * DMODEL + col] =
                packbf(o[mi][nt][2] * inv1, o[mi][nt][3] * inv1);
        }
    }
}

// ---------------- gating + fused offsets/tile-list (last block) ---------------
__global__ __launch_bounds__(128) void gate_topk(
    const float* __restrict__ xn, const float* __restrict__ gw,
    const float* __restrict__ gb)
{
    int warp = threadIdx.x >> 5;
    int lane = threadIdx.x & 31;
    int t = blockIdx.x * 4 + warp;
    float acc[NEXP];
    #pragma unroll
    for (int e = 0; e < NEXP; e++) acc[e] = 0.f;
    for (int d = lane; d < DMODEL; d += 32) {
        float xv = xn[(size_t)t * DMODEL + d];
        #pragma unroll
        for (int e = 0; e < NEXP; e++) acc[e] = fmaf(xv, gw[e * DMODEL + d], acc[e]);
    }
    #pragma unroll
    for (int e = 0; e < NEXP; e++)
        #pragma unroll
        for (int o = 16; o > 0; o >>= 1)
            acc[e] += __shfl_xor_sync(0xffffffffu, acc[e], o);
    if (lane == 0) {
        float lg[NEXP];
        float mx = -1e30f;
        #pragma unroll
        for (int e = 0; e < NEXP; e++) { lg[e] = acc[e] + gb[e]; mx = fmaxf(mx, lg[e]); }
        float sum = 0.f;
        #pragma unroll
        for (int e = 0; e < NEXP; e++) { lg[e] = __expf(lg[e] - mx); sum += lg[e]; }
        float inv = 1.f / sum;
        int e0 = 0; float p0 = lg[0];
        #pragma unroll
        for (int e = 1; e < NEXP; e++) if (lg[e] > p0) { p0 = lg[e]; e0 = e; }
        int e1 = -1; float p1 = -1.f;
        #pragma unroll
        for (int e = 0; e < NEXP; e++)
            if (e != e0 && lg[e] > p1) { p1 = lg[e]; e1 = e; }
        g_tidx[t * 2] = e0;         g_tidx[t * 2 + 1] = e1;
        g_tscale[t * 2] = p0 * inv; g_tscale[t * 2 + 1] = p1 * inv;
        atomicAdd(&g_counts[e0], 1);
        atomicAdd(&g_counts[e1], 1);
    }
    // completion ticket: last block computes offsets + tile list
    __syncthreads();
    __shared__ int lastS;
    if (threadIdx.x == 0) {
        __threadfence();
        lastS = (atomicAdd(&g_gateDone, 1) == (int)gridDim.x - 1);
    }
    __syncthreads();
    if (lastS && threadIdx.x == 0) {
        int o = 0, nt = 0;
        for (int e = 0; e < NEXP; e++) {
            g_off[e] = o;
            o += g_counts[e];
        }
        for (int e = 0; e < NEXP; e++)
            for (int bm = 0; bm < g_counts[e]; bm += 128) {
                g_tileE[nt] = e;
                g_tileBm[nt] = bm;
                nt++;
            }
        g_ntiles = nt;
        __threadfence();
    }
}

__global__ __launch_bounds__(256) void assign_rows()
{
    int p = blockIdx.x * 256 + threadIdx.x;
    if (p >= NPAIR) return;
    int e = g_tidx[p];
    int pos = g_off[e] + atomicAdd(&g_cursor[e], 1);
    g_rowTok[pos] = p >> 1;
    g_rowScale[pos] = g_tscale[p];
    g_pairRow[p] = pos;
}

// ---------------- launch -----------------------------------------------------
extern "C" void kernel_launch(void* const* d_in, const int* in_sizes, int n_in,
                              void* d_out, int out_size)
{
    const float* src        = (const float*)d_in[0];
    const float* in_proj_w  = (const float*)d_in[1];
    const float* in_proj_b  = (const float*)d_in[2];
    const float* out_proj_w = (const float*)d_in[3];
    const float* out_proj_b = (const float*)d_in[4];
    const float* ln1_g      = (const float*)d_in[5];
    const float* ln1_b      = (const float*)d_in[6];
    const float* ln2_g      = (const float*)d_in[7];
    const float* ln2_b      = (const float*)d_in[8];
    const float* gate_w     = (const float*)d_in[9];
    const float* gate_b     = (const float*)d_in[10];
    const float* w1         = (const float*)d_in[11];
    const float* b1         = (const float*)d_in[12];
    const float* w2         = (const float*)d_in[13];
    const float* b2         = (const float*)d_in[14];
    const float* wo         = (const float*)d_in[15];
    const float* bo         = (const float*)d_in[16];
    float* out = (float*)d_out;

    float *xn;
    __nv_bfloat16 *xnb, *qkvb, *attnb, *bwin, *bwout;
    cudaGetSymbolAddress((void**)&xn,    g_xn);
    cudaGetSymbolAddress((void**)&xnb,   g_xnb);
    cudaGetSymbolAddress((void**)&qkvb,  g_qkvb);
    cudaGetSymbolAddress((void**)&attnb, g_attnb);
    cudaGetSymbolAddress((void**)&bwin,  g_bwin);
    cudaGetSymbolAddress((void**)&bwout, g_bwout);

    cudaFuncSetAttribute(flash_attn_bf16,
                         cudaFuncAttributeMaxDynamicSharedMemorySize,
                         ATTN_SMEM_BYTES);
    cudaFuncSetAttribute(gemm_bf16_nt,
                         cudaFuncAttributeMaxDynamicSharedMemorySize, GEMM_SMEM_BYTES);
    cudaFuncSetAttribute(gemm_qkv,
                         cudaFuncAttributeMaxDynamicSharedMemorySize, GEMM_SMEM_BYTES);
    cudaFuncSetAttribute(moe_up1,
                         cudaFuncAttributeMaxDynamicSharedMemorySize, GEMM_SMEM_BYTES);
    cudaFuncSetAttribute(moe_up2,
                         cudaFuncAttributeMaxDynamicSharedMemorySize, GEMM_SMEM_BYTES);
    cudaFuncSetAttribute(moe_down,
                         cudaFuncAttributeMaxDynamicSharedMemorySize, GEMM_SMEM_BYTES);

    // fused weight convert + counter init
    f2bf_all<<<3200, 256>>>(in_proj_w, out_proj_w, w1, w2, wo);

    // ---- attention block ----
    layernorm_k<<<SEQ, 128>>>(src, ln1_g, ln1_b, xn, xnb);
    gemm_qkv<<<dim3(12, 32), 256, GEMM_SMEM_BYTES>>>(xnb, bwin, in_proj_b, qkvb,
                                                     SEQ, 3 * DMODEL, DMODEL);
    flash_attn_bf16<<<dim3(SEQ / 128, NHEAD), 128, ATTN_SMEM_BYTES>>>(qkvb, attnb);
    gemm_bf16_nt<<<dim3(4, 32), 256, GEMM_SMEM_BYTES>>>(attnb, bwout, out_proj_b,
                                                        src, out, SEQ, DMODEL, DMODEL);

    // ---- MoE block ----
    layernorm_k<<<SEQ, 128>>>(out, ln2_g, ln2_b, xn, xnb);
    gate_topk<<<SEQ / 4, 128>>>(xn, gate_w, gate_b);   // fused offsets/tile list
    assign_rows<<<NPAIR / 256, 256>>>();
    moe_up1<<<dim3(FDIM / 128, MAXTILE - 8), 256, GEMM_SMEM_BYTES>>>(b1);
    moe_up2<<<dim3(FDIM / 128, MAXTILE - 8), 256, GEMM_SMEM_BYTES>>>(b2);
    moe_down<<<dim3(DMODEL / 128, MAXTILE - 8), 256, GEMM_SMEM_BYTES>>>(bo);
    moe_combine<<<SEQ, 128>>>(out);
}

// round 17
// speedup vs baseline: 1.0812x; 1.0261x over previous
#include <cuda_runtime.h>
#include <cuda_bf16.h>
#include <math.h>

#define SEQ 4096
#define DMODEL 512
#define NHEAD 8
#define FDIM 2048
#define NEXP 8
#define NPAIR (SEQ * 2)
#define MAXTILE 80
#define NSPLIT 4
#define KVSPAN (SEQ / NSPLIT)

// ---------------- scratch (device globals; no allocations allowed) ----------
__device__ float g_xn[SEQ * DMODEL];
__device__ __nv_bfloat16 g_xnb[SEQ * DMODEL];
__device__ __nv_bfloat16 g_qkvb[SEQ * 3 * DMODEL];
__device__ __nv_bfloat16 g_attnb[SEQ * DMODEL];
__device__ __nv_bfloat16 g_h1b[NPAIR * FDIM];
__device__ __nv_bfloat16 g_hb[NPAIR * FDIM];
__device__ float g_dout[NPAIR * DMODEL];
__device__ float g_po[NSPLIT * SEQ * NHEAD * 64];   // unnormalized O partials
__device__ float g_pm[NSPLIT * SEQ * NHEAD];        // running max (log2 domain)
__device__ float g_pl[NSPLIT * SEQ * NHEAD];        // running sum
__device__ __nv_bfloat16 g_bwin[3 * DMODEL * DMODEL];
__device__ __nv_bfloat16 g_bwout[DMODEL * DMODEL];
__device__ __nv_bfloat16 g_bw1[NEXP * FDIM * DMODEL];
__device__ __nv_bfloat16 g_bw2[NEXP * FDIM * DMODEL];
__device__ __nv_bfloat16 g_bwo[NEXP * DMODEL * FDIM];
__device__ int   g_tidx[NPAIR];
__device__ float g_tscale[NPAIR];
__device__ int   g_counts[NEXP];
__device__ int   g_cursor[NEXP];
__device__ int   g_off[NEXP];
__device__ float g_rowScale[NPAIR];
__device__ int   g_rowTok[NPAIR];
__device__ int   g_pairRow[NPAIR];
__device__ int   g_tileE[MAXTILE];
__device__ int   g_tileBm[MAXTILE];
__device__ int   g_ntiles;
__device__ int   g_gateDone;

// ---------------- helpers -----------------------------------------------------
__device__ __forceinline__ void mma16(float c[4],
    unsigned a0, unsigned a1, unsigned a2, unsigned a3,
    unsigned b0, unsigned b1)
{
    asm volatile(
        "mma.sync.aligned.m16n8k16.row.col.f32.bf16.bf16.f32 "
        "{%0,%1,%2,%3}, {%4,%5,%6,%7}, {%8,%9}, {%0,%1,%2,%3};\n"
        : "+f"(c[0]), "+f"(c[1]), "+f"(c[2]), "+f"(c[3])
        : "r"(a0), "r"(a1), "r"(a2), "r"(a3), "r"(b0), "r"(b1));
}

__device__ __forceinline__ void ldsm4(unsigned& r0, unsigned& r1,
                                      unsigned& r2, unsigned& r3, unsigned addr)
{
    asm volatile(
        "ldmatrix.sync.aligned.m8n8.x4.shared.b16 {%0,%1,%2,%3}, [%4];\n"
        : "=r"(r0), "=r"(r1), "=r"(r2), "=r"(r3) : "r"(addr));
}

__device__ __forceinline__ void ldsm4t(unsigned& r0, unsigned& r1,
                                       unsigned& r2, unsigned& r3, unsigned addr)
{
    asm volatile(
        "ldmatrix.sync.aligned.m8n8.x4.trans.shared.b16 {%0,%1,%2,%3}, [%4];\n"
        : "=r"(r0), "=r"(r1), "=r"(r2), "=r"(r3) : "r"(addr));
}

__device__ __forceinline__ unsigned smem_u32(const void* p) {
    return (unsigned)__cvta_generic_to_shared(p);
}
__device__ __forceinline__ void cpa16(unsigned dst, const void* src, int vbytes) {
    asm volatile("cp.async.cg.shared.global [%0], [%1], 16, %2;\n"
                 :: "r"(dst), "l"(src), "r"(vbytes) : "memory");
}
__device__ __forceinline__ void cpa_commit() {
    asm volatile("cp.async.commit_group;\n" ::: "memory");
}
__device__ __forceinline__ unsigned packbf(float a, float b) {
    __nv_bfloat162 p = __floats2bfloat162_rn(a, b);
    return *(unsigned*)&p;
}

#define LDSM_OFFS() \
    const int rl_ = lane & 7, quad_ = lane >> 3; \
    const int arow_off = rl_ + ((quad_ & 1) << 3); \
    const int acol_off = (quad_ >> 1) << 2; \
    const int brow_off = rl_ + ((quad_ >> 1) << 3); \
    const int bcol_off = (quad_ & 1) << 2;

// ---------------- fused fp32 -> bf16 convert + counter init -------------------
__global__ __launch_bounds__(256) void f2bf_all(
    const float* __restrict__ w_in, const float* __restrict__ w_out,
    const float* __restrict__ w1, const float* __restrict__ w2,
    const float* __restrict__ wo)
{
    if (blockIdx.x == 0 && threadIdx.x < NEXP + 1) {
        if (threadIdx.x < NEXP) {
            g_counts[threadIdx.x] = 0;
            g_cursor[threadIdx.x] = 0;
        } else {
            g_gateDone = 0;
        }
    }
    int blk = blockIdx.x;
    const float4* src;
    uint2* dst;
    size_t base;
    if (blk < 96)        { src = (const float4*)w_in;  dst = (uint2*)g_bwin;  base = (size_t)blk * 2048; }
    else if (blk < 128)  { src = (const float4*)w_out; dst = (uint2*)g_bwout; base = (size_t)(blk - 96) * 2048; }
    else if (blk < 1152) { src = (const float4*)w1;    dst = (uint2*)g_bw1;   base = (size_t)(blk - 128) * 2048; }
    else if (blk < 2176) { src = (const float4*)w2;    dst = (uint2*)g_bw2;   base = (size_t)(blk - 1152) * 2048; }
    else                 { src = (const float4*)wo;    dst = (uint2*)g_bwo;   base = (size_t)(blk - 2176) * 2048; }
    size_t i0 = base + threadIdx.x;
    float4 v[8];
    #pragma unroll
    for (int j = 0; j < 8; j++) v[j] = src[i0 + j * 256];
    #pragma unroll
    for (int j = 0; j < 8; j++) {
        uint2 u; u.x = packbf(v[j].x, v[j].y); u.y = packbf(v[j].z, v[j].w);
        dst[i0 + j * 256] = u;
    }
}

// ---------------- layernorm (dual fp32 + bf16 output) -------------------------
__global__ __launch_bounds__(128) void layernorm_k(
    const float* __restrict__ x, const float* __restrict__ g,
    const float* __restrict__ b, float* __restrict__ y,
    __nv_bfloat16* __restrict__ yb)
{
    int t = blockIdx.x;
    int tid = threadIdx.x;
    float4 v = ((const float4*)(x + (size_t)t * DMODEL))[tid];
    float s  = v.x + v.y + v.z + v.w;
    float ss = v.x * v.x + v.y * v.y + v.z * v.z + v.w * v.w;
    #pragma unroll
    for (int o = 16; o > 0; o >>= 1) {
        s  += __shfl_xor_sync(0xffffffffu, s, o);
        ss += __shfl_xor_sync(0xffffffffu, ss, o);
    }
    __shared__ float sw[4], ssw[4];
    __shared__ float meanS, rstdS;
    int lane = tid & 31, w = tid >> 5;
    if (lane == 0) { sw[w] = s; ssw[w] = ss; }
    __syncthreads();
    if (tid == 0) {
        float S = sw[0] + sw[1] + sw[2] + sw[3];
        float SS = ssw[0] + ssw[1] + ssw[2] + ssw[3];
        float mean = S / (float)DMODEL;
        float var = SS / (float)DMODEL - mean * mean;
        meanS = mean;
        rstdS = rsqrtf(var + 1e-5f);
    }
    __syncthreads();
    float mean = meanS, rstd = rstdS;
    float4 gg = ((const float4*)g)[tid];
    float4 bb = ((const float4*)b)[tid];
    float4 o;
    o.x = (v.x - mean) * rstd * gg.x + bb.x;
    o.y = (v.y - mean) * rstd * gg.y + bb.y;
    o.z = (v.z - mean) * rstd * gg.z + bb.z;
    o.w = (v.w - mean) * rstd * gg.w + bb.w;
    ((float4*)(y + (size_t)t * DMODEL))[tid] = o;
    uint2 u; u.x = packbf(o.x, o.y); u.y = packbf(o.z, o.w);
    ((uint2*)(yb + (size_t)t * DMODEL))[tid] = u;
}

// ---------------- bf16 GEMM core: 3-stage cp.async, BK=32 (frozen) ------------
#define GEMM_SMEM_BYTES (3 * 20480)

__device__ __forceinline__ void gemm_bf16_core(
    const __nv_bfloat16* __restrict__ Ar, int av,
    const __nv_bfloat16* __restrict__ B,
    int K, int bn, unsigned* su, float c[4][4][4])
{
    const int tid = threadIdx.x;
    const int lane = tid & 31;
    const int w = tid >> 5, wm = (w >> 2) << 6, wn = (w & 3) << 5;
    LDSM_OFFS();
    const int r = tid >> 1;
    const int seg0 = (tid & 1) << 1;
    const int nk = K >> 5;
    const __nv_bfloat16* Br = B + (size_t)(bn + r) * K;
    const unsigned suB = smem_u32(su);
    const unsigned dstA0 = suB + (unsigned)(r * 20) * 4;

    #define GEMM_ISSUE(kt_, st_) do {                                        \
        int k0_ = (kt_) << 5;                                                \
        unsigned sb_ = (unsigned)(st_) * 20480u;                             \
        _Pragma("unroll")                                                    \
        for (int i_ = 0; i_ < 2; i_++) {                                     \
            int seg_ = seg0 + i_;                                            \
            cpa16(dstA0 + sb_ + seg_ * 16, Ar + k0_ + seg_ * 8, av);         \
            cpa16(dstA0 + sb_ + 10240 + seg_ * 16, Br + k0_ + seg_ * 8, 16); \
        }                                                                    \
        cpa_commit();                                                        \
    } while (0)

    GEMM_ISSUE(0, 0);
    GEMM_ISSUE(1, 1);

    int stC = 0, stI = 2;
    for (int kt = 0; kt < nk; kt++) {
        if (kt < nk - 1) asm volatile("cp.async.wait_group 1;\n" ::: "memory");
        else             asm volatile("cp.async.wait_group 0;\n" ::: "memory");
        __syncthreads();
        if (kt + 2 < nk) GEMM_ISSUE(kt + 2, stI);
        const unsigned stageA = suB + (unsigned)stC * 20480u;
        const unsigned stageB = stageA + 10240u;
        #pragma unroll
        for (int kk = 0; kk < 2; kk++) {
            const int kb = kk << 3;
            unsigned a[4][4], b[4][2];
            const unsigned aAddr =
                stageA + (unsigned)((wm + arow_off) * 20 + kb + acol_off) * 4;
            #pragma unroll
            for (int mi = 0; mi < 4; mi++)
                ldsm4(a[mi][0], a[mi][1], a[mi][2], a[mi][3],
                      aAddr + (unsigned)(mi * 16 * 20) * 4);
            const unsigned bAddr =
                stageB + (unsigned)((wn + brow_off) * 20 + kb + bcol_off) * 4;
            ldsm4(b[0][0], b[0][1], b[1][0], b[1][1], bAddr);
            ldsm4(b[2][0], b[2][1], b[3][0], b[3][1],
                  bAddr + (unsigned)(16 * 20) * 4);
            #pragma unroll
            for (int mi = 0; mi < 4; mi++)
                #pragma unroll
                for (int ni = 0; ni < 4; ni++)
                    mma16(c[mi][ni], a[mi][0], a[mi][1], a[mi][2], a[mi][3],
                          b[ni][0], b[ni][1]);
        }
        stC = (stC == 2) ? 0 : stC + 1;
        stI = (stI == 2) ? 0 : stI + 1;
    }
    #undef GEMM_ISSUE
}

#define GEMM_PROLOGUE() \
    extern __shared__ unsigned su[]; \
    float c[4][4][4]; \
    _Pragma("unroll") \
    for (int mi = 0; mi < 4; mi++) \
        _Pragma("unroll") \
        for (int ni = 0; ni < 4; ni++) \
            _Pragma("unroll") \
            for (int j = 0; j < 4; j++) c[mi][ni][j] = 0.f; \
    const int lane = threadIdx.x & 31; \
    const int g = lane >> 2, tig = lane & 3; \
    const int w = threadIdx.x >> 5; \
    const int wm = (w >> 2) << 6, wn = (w & 3) << 5;

#define DENSE_AROW(Abase, Kd) \
    const int r_ = threadIdx.x >> 1; \
    const int arow_ = (bm + r_ < M) ? (bm + r_) : 0; \
    const int av = (bm + r_ < M) ? 16 : 0; \
    const __nv_bfloat16* Ar = (Abase) + (size_t)arow_ * (Kd);

__global__ __launch_bounds__(256, 2) void gemm_bf16_nt(
    const __nv_bfloat16* __restrict__ A, const __nv_bfloat16* __restrict__ B,
    const float* __restrict__ bias, const float* __restrict__ resid,
    float* __restrict__ C, int M, int N, int K)
{
    const int bm = blockIdx.y * 128;
    const int bn = blockIdx.x * 128;
    GEMM_PROLOGUE();
    DENSE_AROW(A, K);
    gemm_bf16_core(Ar, av, B, K, bn, su, c);
    #pragma unroll
    for (int mi = 0; mi < 4; mi++)
        #pragma unroll
        for (int half = 0; half < 2; half++) {
            int row = bm + wm + (mi << 4) + g + half * 8;
            if (row >= M) continue;
            #pragma unroll
            for (int ni = 0; ni < 4; ni++) {
                int col = bn + wn + (ni << 3) + 2 * tig;
                float v0 = c[mi][ni][half * 2]     + bias[col];
                float v1 = c[mi][ni][half * 2 + 1] + bias[col + 1];
                if (resid) {
                    v0 += resid[(size_t)row * N + col];
                    v1 += resid[(size_t)row * N + col + 1];
                }
                float2 v; v.x = v0; v.y = v1;
                *(float2*)&C[(size_t)row * N + col] = v;
            }
        }
}

// QKV GEMM: bf16 out; Q columns pre-scaled by 0.125*log2(e) (exp2 softmax).
__global__ __launch_bounds__(256, 2) void gemm_qkv(
    const __nv_bfloat16* __restrict__ A, const __nv_bfloat16* __restrict__ B,
    const float* __restrict__ bias, __nv_bfloat16* __restrict__ C,
    int M, int N, int K)
{
    const int bm = blockIdx.y * 128;
    const int bn = blockIdx.x * 128;
    GEMM_PROLOGUE();
    DENSE_AROW(A, K);
    gemm_bf16_core(Ar, av, B, K, bn, su, c);
    const float QSC = 0.125f * 1.4426950408889634f;
    #pragma unroll
    for (int mi = 0; mi < 4; mi++)
        #pragma unroll
        for (int half = 0; half < 2; half++) {
            int row = bm + wm + (mi << 4) + g + half * 8;
            #pragma unroll
            for (int ni = 0; ni < 4; ni++) {
                int col = bn + wn + (ni << 3) + 2 * tig;
                float sc = (col < DMODEL) ? QSC : 1.f;
                float v0 = (c[mi][ni][half * 2]     + bias[col]) * sc;
                float v1 = (c[mi][ni][half * 2 + 1] + bias[col + 1]) * sc;
                *(unsigned*)&C[(size_t)row * N + col] = packbf(v0, v1);
            }
        }
}

#define MOE_AROW() \
    const int r_ = threadIdx.x >> 1; \
    const bool vld_ = (bm + r_ < M); \
    const int tok_ = vld_ ? g_rowTok[g_off[e] + bm + r_] : 0; \
    const int av = vld_ ? 16 : 0; \
    const __nv_bfloat16* Ar = g_xnb + (size_t)tok_ * DMODEL;

__global__ __launch_bounds__(256, 2) void moe_up1(const float* __restrict__ Ball)
{
    int ti = blockIdx.y;
    if (ti >= g_ntiles) return;
    int e = g_tileE[ti];
    int bm = g_tileBm[ti];
    int M = g_counts[e];
    int bn = blockIdx.x * 128;
    const __nv_bfloat16* B = g_bw1 + (size_t)e * FDIM * DMODEL;
    const float* bias = Ball + (size_t)e * FDIM;
    __nv_bfloat16* C = g_h1b + (size_t)g_off[e] * FDIM;
    GEMM_PROLOGUE();
    MOE_AROW();
    gemm_bf16_core(Ar, av, B, DMODEL, bn, su, c);
    #pragma unroll
    for (int mi = 0; mi < 4; mi++)
        #pragma unroll
        for (int half = 0; half < 2; half++) {
            int row = bm + wm + (mi << 4) + g + half * 8;
            if (row >= M) continue;
            #pragma unroll
            for (int ni = 0; ni < 4; ni++) {
                int col = bn + wn + (ni << 3) + 2 * tig;
                *(unsigned*)&C[(size_t)row * FDIM + col] =
                    packbf(c[mi][ni][half * 2]     + bias[col],
                           c[mi][ni][half * 2 + 1] + bias[col + 1]);
            }
        }
}

__global__ __launch_bounds__(256, 2) void moe_up2(const float* __restrict__ Ball)
{
    int ti = blockIdx.y;
    if (ti >= g_ntiles) return;
    int e = g_tileE[ti];
    int bm = g_tileBm[ti];
    int M = g_counts[e];
    int bn = blockIdx.x * 128;
    const __nv_bfloat16* B = g_bw2 + (size_t)e * FDIM * DMODEL;
    const float* bias = Ball + (size_t)e * FDIM;
    const __nv_bfloat16* H1 = g_h1b + (size_t)g_off[e] * FDIM;
    __nv_bfloat16* HB = g_hb + (size_t)g_off[e] * FDIM;
    GEMM_PROLOGUE();
    MOE_AROW();
    gemm_bf16_core(Ar, av, B, DMODEL, bn, su, c);
    #pragma unroll
    for (int mi = 0; mi < 4; mi++)
        #pragma unroll
        for (int half = 0; half < 2; half++) {
            int row = bm + wm + (mi << 4) + g + half * 8;
            if (row >= M) continue;
            #pragma unroll
            for (int ni = 0; ni < 4; ni++) {
                int col = bn + wn + (ni << 3) + 2 * tig;
                unsigned hv = *(const unsigned*)&H1[(size_t)row * FDIM + col];
                __nv_bfloat162 hb2 = *(__nv_bfloat162*)&hv;
                float gx = __bfloat162float(hb2.x);
                float gy = __bfloat162float(hb2.y);
                float h2v0 = c[mi][ni][half * 2]     + bias[col];
                float h2v1 = c[mi][ni][half * 2 + 1] + bias[col + 1];
                float s0 = gx / (1.f + __expf(-gx));
                float s1 = gy / (1.f + __expf(-gy));
                *(unsigned*)&HB[(size_t)row * FDIM + col] = packbf(s0 * h2v0, s1 * h2v1);
            }
        }
}

__global__ __launch_bounds__(256, 2) void moe_down(const float* __restrict__ Bo)
{
    int ti = blockIdx.y;
    if (ti >= g_ntiles) return;
    int e = g_tileE[ti];
    int bm = g_tileBm[ti];
    int M = g_counts[e];
    int bn = blockIdx.x * 128;
    const __nv_bfloat16* A = g_hb + (size_t)g_off[e] * FDIM;
    const __nv_bfloat16* B = g_bwo + (size_t)e * DMODEL * FDIM;
    const float* bias = Bo + (size_t)e * DMODEL;
    GEMM_PROLOGUE();
    DENSE_AROW(A, FDIM);
    gemm_bf16_core(Ar, av, B, FDIM, bn, su, c);
    #pragma unroll
    for (int mi = 0; mi < 4; mi++)
        #pragma unroll
        for (int half = 0; half < 2; half++) {
            int row = bm + wm + (mi << 4) + g + half * 8;
            if (row >= M) continue;
            int gr = g_off[e] + row;
            float sc = g_rowScale[gr];
            #pragma unroll
            for (int ni = 0; ni < 4; ni++) {
                int col = bn + wn + (ni << 3) + 2 * tig;
                float2 v;
                v.x = sc * (c[mi][ni][half * 2]     + bias[col]);
                v.y = sc * (c[mi][ni][half * 2 + 1] + bias[col + 1]);
                *(float2*)&g_dout[(size_t)gr * DMODEL + col] = v;
            }
        }
}

__global__ __launch_bounds__(128) void moe_combine(float* __restrict__ Out)
{
    int t = blockIdx.x;
    int tid = threadIdx.x;
    int r0 = g_pairRow[t * 2];
    int r1 = g_pairRow[t * 2 + 1];
    float4 a = ((const float4*)(g_dout + (size_t)r0 * DMODEL))[tid];
    float4 b = ((const float4*)(g_dout + (size_t)r1 * DMODEL))[tid];
    float4 o = ((const float4*)(Out + (size_t)t * DMODEL))[tid];
    o.x += a.x + b.x; o.y += a.y + b.y;
    o.z += a.z + b.z; o.w += a.w + b.w;
    ((float4*)(Out + (size_t)t * DMODEL))[tid] = o;
}

// ---------------- bf16 flash attention, split-KV=4, exp2 softmax --------------
// Bq=128, 128 threads (4 warps); warp owns 32 q-rows. Each CTA covers 1024 keys.
// Writes unnormalized O + (m,l) partials; attn_combine merges the 4 splits.
#define ATTN_STAGE_U32 (2 * 64 * 36)
#define ATTN_SMEM_BYTES ((128 * 36 + 3 * ATTN_STAGE_U32) * 4)

__global__ __launch_bounds__(128, 3) void flash_attn_bf16(
    const __nv_bfloat16* __restrict__ qkv)
{
    extern __shared__ unsigned asm_[];
    unsigned (*Qu)[36] = (unsigned(*)[36])asm_;
    unsigned* kvbase = asm_ + 128 * 36;

    const int tid = threadIdx.x;
    const int w = tid >> 5, lane = tid & 31;
    const int g = lane >> 2, tig = lane & 3;
    LDSM_OFFS();
    const int h = blockIdx.y;
    const int q0 = blockIdx.x * 128;
    const int z = blockIdx.z;
    const int kv0 = z * KVSPAN;
    const int m0 = w * 32;
    const int nkt = KVSPAN / 64;
    const unsigned kvB = smem_u32(kvbase);

    #define KV_ISSUE(kt_, st_) do {                                              \
        int kr0_ = kv0 + ((kt_) << 6);                                           \
        unsigned sb_ = kvB + (unsigned)(st_) * (ATTN_STAGE_U32 * 4);             \
        _Pragma("unroll")                                                        \
        for (int i_ = 0; i_ < 4; i_++) {                                         \
            int f_ = tid + i_ * 128;                                             \
            int col_ = f_ >> 3, ch_ = f_ & 7;                                    \
            const __nv_bfloat16* base_ =                                         \
                qkv + (size_t)(kr0_ + col_) * 1536 + 512 + h * 64 + ch_ * 8;     \
            unsigned ko_ = sb_ + (unsigned)(col_ * 36 + ch_ * 4) * 4;            \
            cpa16(ko_, base_, 16);                                               \
            cpa16(ko_ + 64 * 36 * 4, base_ + 512, 16);                           \
        }                                                                        \
        cpa_commit();                                                            \
    } while (0)

    KV_ISSUE(0, 0);
    KV_ISSUE(1, 1);

    #pragma unroll
    for (int i = 0; i < 8; i++) {
        int f = tid + i * 128;
        int rq = f >> 3, u4 = (f & 7) << 2;
        *(uint4*)&Qu[rq][u4] =
            *(const uint4*)(qkv + (size_t)(q0 + rq) * 1536 + h * 64 + (u4 << 1));
    }

    float o[2][8][4];
    #pragma unroll
    for (int mi = 0; mi < 2; mi++)
        #pragma unroll
        for (int nt = 0; nt < 8; nt++)
            #pragma unroll
            for (int j = 0; j < 4; j++) o[mi][nt][j] = 0.f;
    float mr[2][2] = {{-1e30f, -1e30f}, {-1e30f, -1e30f}};
    float lr[2][2] = {{0.f, 0.f}, {0.f, 0.f}};

    const int lt = lane >> 3, lrow = lane & 7;
    const int koff = ((lt & 1) << 3) + lrow;
    const int doff = (lt >> 1) << 2;

    int stC = 0, stI = 2;
    for (int kt = 0; kt < nkt; kt++) {
        if (kt < nkt - 1) asm volatile("cp.async.wait_group 1;\n" ::: "memory");
        else              asm volatile("cp.async.wait_group 0;\n" ::: "memory");
        __syncthreads();
        if (kt + 2 < nkt) KV_ISSUE(kt + 2, stI);
        unsigned (*Ku)[36] = (unsigned(*)[36])(kvbase + stC * ATTN_STAGE_U32);
        unsigned (*Vu)[36] = Ku + 64;

        float s[2][8][4];
        #pragma unroll
        for (int mi = 0; mi < 2; mi++)
            #pragma unroll
            for (int nt = 0; nt < 8; nt++)
                #pragma unroll
                for (int j = 0; j < 4; j++) s[mi][nt][j] = 0.f;
        #pragma unroll
        for (int ktt = 0; ktt < 4; ktt++) {
            const int kb = ktt << 3;
            unsigned a[2][4];
            #pragma unroll
            for (int mi = 0; mi < 2; mi++)
                ldsm4(a[mi][0], a[mi][1], a[mi][2], a[mi][3],
                      smem_u32(&Qu[m0 + (mi << 4) + arow_off][kb + acol_off]));
            #pragma unroll
            for (int ntp = 0; ntp < 4; ntp++) {
                unsigned b00, b01, b10, b11;
                ldsm4(b00, b01, b10, b11,
                      smem_u32(&Ku[(ntp << 4) + brow_off][kb + bcol_off]));
                mma16(s[0][2*ntp],   a[0][0], a[0][1], a[0][2], a[0][3], b00, b01);
                mma16(s[1][2*ntp],   a[1][0], a[1][1], a[1][2], a[1][3], b00, b01);
                mma16(s[0][2*ntp+1], a[0][0], a[0][1], a[0][2], a[0][3], b10, b11);
                mma16(s[1][2*ntp+1], a[1][0], a[1][1], a[1][2], a[1][3], b10, b11);
            }
        }

        // online softmax in registers (log2 domain: scores pre-scaled by log2e)
        #pragma unroll
        for (int mi = 0; mi < 2; mi++) {
            float mx0 = mr[mi][0], mx1 = mr[mi][1];
            #pragma unroll
            for (int nt = 0; nt < 8; nt++) {
                mx0 = fmaxf(mx0, fmaxf(s[mi][nt][0], s[mi][nt][1]));
                mx1 = fmaxf(mx1, fmaxf(s[mi][nt][2], s[mi][nt][3]));
            }
            mx0 = fmaxf(mx0, __shfl_xor_sync(0xffffffffu, mx0, 1));
            mx0 = fmaxf(mx0, __shfl_xor_sync(0xffffffffu, mx0, 2));
            mx1 = fmaxf(mx1, __shfl_xor_sync(0xffffffffu, mx1, 1));
            mx1 = fmaxf(mx1, __shfl_xor_sync(0xffffffffu, mx1, 2));
            float al0 = exp2f(mr[mi][0] - mx0);
            float al1 = exp2f(mr[mi][1] - mx1);
            float sum0 = 0.f, sum1 = 0.f;
            #pragma unroll
            for (int nt = 0; nt < 8; nt++) {
                s[mi][nt][0] = exp2f(s[mi][nt][0] - mx0);
                s[mi][nt][1] = exp2f(s[mi][nt][1] - mx0);
                s[mi][nt][2] = exp2f(s[mi][nt][2] - mx1);
                s[mi][nt][3] = exp2f(s[mi][nt][3] - mx1);
                sum0 += s[mi][nt][0] + s[mi][nt][1];
                sum1 += s[mi][nt][2] + s[mi][nt][3];
            }
            sum0 += __shfl_xor_sync(0xffffffffu, sum0, 1);
            sum0 += __shfl_xor_sync(0xffffffffu, sum0, 2);
            sum1 += __shfl_xor_sync(0xffffffffu, sum1, 1);
            sum1 += __shfl_xor_sync(0xffffffffu, sum1, 2);
            lr[mi][0] = lr[mi][0] * al0 + sum0; mr[mi][0] = mx0;
            lr[mi][1] = lr[mi][1] * al1 + sum1; mr[mi][1] = mx1;
            #pragma unroll
            for (int nt = 0; nt < 8; nt++) {
                o[mi][nt][0] *= al0; o[mi][nt][1] *= al0;
                o[mi][nt][2] *= al1; o[mi][nt][3] *= al1;
            }
        }

        #pragma unroll
        for (int ktt = 0; ktt < 4; ktt++) {
            unsigned a[2][4];
            #pragma unroll
            for (int mi = 0; mi < 2; mi++) {
                a[mi][0] = packbf(s[mi][2*ktt][0],   s[mi][2*ktt][1]);
                a[mi][1] = packbf(s[mi][2*ktt][2],   s[mi][2*ktt][3]);
                a[mi][2] = packbf(s[mi][2*ktt+1][0], s[mi][2*ktt+1][1]);
                a[mi][3] = packbf(s[mi][2*ktt+1][2], s[mi][2*ktt+1][3]);
            }
            const int krow = (ktt << 4) + koff;
            #pragma unroll
            for (int ntp = 0; ntp < 4; ntp++) {
                unsigned b0, b1, b2, b3;
                ldsm4t(b0, b1, b2, b3,
                       smem_u32(&Vu[krow][(ntp << 3) + doff]));
                mma16(o[0][2*ntp],   a[0][0], a[0][1], a[0][2], a[0][3], b0, b1);
                mma16(o[1][2*ntp],   a[1][0], a[1][1], a[1][2], a[1][3], b0, b1);
                mma16(o[0][2*ntp+1], a[0][0], a[0][1], a[0][2], a[0][3], b2, b3);
                mma16(o[1][2*ntp+1], a[1][0], a[1][1], a[1][2], a[1][3], b2, b3);
            }
        }
        stC = (stC == 2) ? 0 : stC + 1;
        stI = (stI == 2) ? 0 : stI + 1;
    }
    #undef KV_ISSUE

    // epilogue: write unnormalized partials for this split
    float* po = g_po + (size_t)z * SEQ * NHEAD * 64;
    float* pm = g_pm + (size_t)z * SEQ * NHEAD;
    float* pl = g_pl + (size_t)z * SEQ * NHEAD;
    #pragma unroll
    for (int mi = 0; mi < 2; mi++) {
        int mb = m0 + (mi << 4);
        int pr0 = (q0 + mb + g) * NHEAD + h;
        int pr1 = (q0 + mb + g + 8) * NHEAD + h;
        #pragma unroll
        for (int nt = 0; nt < 8; nt++) {
            int col = (nt << 3) + 2 * tig;
            float2 v0; v0.x = o[mi][nt][0]; v0.y = o[mi][nt][1];
            *(float2*)&po[(size_t)pr0 * 64 + col] = v0;
            float2 v1; v1.x = o[mi][nt][2]; v1.y = o[mi][nt][3];
            *(float2*)&po[(size_t)pr1 * 64 + col] = v1;
        }
        if (tig == 0) {
            pm[pr0] = mr[mi][0]; pl[pr0] = lr[mi][0];
            pm[pr1] = mr[mi][1]; pl[pr1] = lr[mi][1];
        }
    }
}

// merge NSPLIT partial softmaxes -> bf16 attention output
__global__ __launch_bounds__(128) void attn_combine(__nv_bfloat16* __restrict__ outb)
{
    int row = blockIdx.x;
    int tid = threadIdx.x;
    int h = tid >> 4;
    int c4 = (tid & 15) << 2;
    int idx = row * NHEAD + h;
    float m[NSPLIT];
    float M = -1e30f;
    #pragma unroll
    for (int s = 0; s < NSPLIT; s++) {
        m[s] = g_pm[(size_t)s * SEQ * NHEAD + idx];
        M = fmaxf(M, m[s]);
    }
    float lsum = 0.f;
    float ax = 0.f, ay = 0.f, az = 0.f, aw = 0.f;
    #pragma unroll
    for (int s = 0; s < NSPLIT; s++) {
        float wgt = exp2f(m[s] - M);
        lsum += wgt * g_pl[(size_t)s * SEQ * NHEAD + idx];
        float4 v = *(const float4*)&g_po[((size_t)s * SEQ * NHEAD + idx) * 64 + c4];
        ax += wgt * v.x; ay += wgt * v.y; az += wgt * v.z; aw += wgt * v.w;
    }
    float inv = 1.f / lsum;
    uint2 u;
    u.x = packbf(ax * inv, ay * inv);
    u.y = packbf(az * inv, aw * inv);
    *(uint2*)&outb[(size_t)row * DMODEL + h * 64 + c4] = u;
}

// ---------------- gating + fused offsets/tile-list (last block) ---------------
__global__ __launch_bounds__(128) void gate_topk(
    const float* __restrict__ xn, const float* __restrict__ gw,
    const float* __restrict__ gb)
{
    int warp = threadIdx.x >> 5;
    int lane = threadIdx.x & 31;
    int t = blockIdx.x * 4 + warp;
    float acc[NEXP];
    #pragma unroll
    for (int e = 0; e < NEXP; e++) acc[e] = 0.f;
    for (int d = lane; d < DMODEL; d += 32) {
        float xv = xn[(size_t)t * DMODEL + d];
        #pragma unroll
        for (int e = 0; e < NEXP; e++) acc[e] = fmaf(xv, gw[e * DMODEL + d], acc[e]);
    }
    #pragma unroll
    for (int e = 0; e < NEXP; e++)
        #pragma unroll
        for (int o = 16; o > 0; o >>= 1)
            acc[e] += __shfl_xor_sync(0xffffffffu, acc[e], o);
    if (lane == 0) {
        float lg[NEXP];
        float mx = -1e30f;
        #pragma unroll
        for (int e = 0; e < NEXP; e++) { lg[e] = acc[e] + gb[e]; mx = fmaxf(mx, lg[e]); }
        float sum = 0.f;
        #pragma unroll
        for (int e = 0; e < NEXP; e++) { lg[e] = __expf(lg[e] - mx); sum += lg[e]; }
        float inv = 1.f / sum;
        int e0 = 0; float p0 = lg[0];
        #pragma unroll
        for (int e = 1; e < NEXP; e++) if (lg[e] > p0) { p0 = lg[e]; e0 = e; }
        int e1 = -1; float p1 = -1.f;
        #pragma unroll
        for (int e = 0; e < NEXP; e++)
            if (e != e0 && lg[e] > p1) { p1 = lg[e]; e1 = e; }
        g_tidx[t * 2] = e0;         g_tidx[t * 2 + 1] = e1;
        g_tscale[t * 2] = p0 * inv; g_tscale[t * 2 + 1] = p1 * inv;
        atomicAdd(&g_counts[e0], 1);
        atomicAdd(&g_counts[e1], 1);
    }
    __syncthreads();
    __shared__ int lastS;
    if (threadIdx.x == 0) {
        __threadfence();
        lastS = (atomicAdd(&g_gateDone, 1) == (int)gridDim.x - 1);
    }
    __syncthreads();
    if (lastS && threadIdx.x == 0) {
        int o = 0, nt = 0;
        for (int e = 0; e < NEXP; e++) {
            g_off[e] = o;
            o += g_counts[e];
        }
        for (int e = 0; e < NEXP; e++)
            for (int bm = 0; bm < g_counts[e]; bm += 128) {
                g_tileE[nt] = e;
                g_tileBm[nt] = bm;
                nt++;
            }
        g_ntiles = nt;
        __threadfence();
    }
}

__global__ __launch_bounds__(256) void assign_rows()
{
    int p = blockIdx.x * 256 + threadIdx.x;
    if (p >= NPAIR) return;
    int e = g_tidx[p];
    int pos = g_off[e] + atomicAdd(&g_cursor[e], 1);
    g_rowTok[pos] = p >> 1;
    g_rowScale[pos] = g_tscale[p];
    g_pairRow[p] = pos;
}

// ---------------- launch -----------------------------------------------------
extern "C" void kernel_launch(void* const* d_in, const int* in_sizes, int n_in,
                              void* d_out, int out_size)
{
    const float* src        = (const float*)d_in[0];
    const float* in_proj_w  = (const float*)d_in[1];
    const float* in_proj_b  = (const float*)d_in[2];
    const float* out_proj_w = (const float*)d_in[3];
    const float* out_proj_b = (const float*)d_in[4];
    const float* ln1_g      = (const float*)d_in[5];
    const float* ln1_b      = (const float*)d_in[6];
    const float* ln2_g      = (const float*)d_in[7];
    const float* ln2_b      = (const float*)d_in[8];
    const float* gate_w     = (const float*)d_in[9];
    const float* gate_b     = (const float*)d_in[10];
    const float* w1         = (const float*)d_in[11];
    const float* b1         = (const float*)d_in[12];
    const float* w2         = (const float*)d_in[13];
    const float* b2         = (const float*)d_in[14];
    const float* wo         = (const float*)d_in[15];
    const float* bo         = (const float*)d_in[16];
    float* out = (float*)d_out;

    float *xn;
    __nv_bfloat16 *xnb, *qkvb, *attnb, *bwin, *bwout;
    cudaGetSymbolAddress((void**)&xn,    g_xn);
    cudaGetSymbolAddress((void**)&xnb,   g_xnb);
    cudaGetSymbolAddress((void**)&qkvb,  g_qkvb);
    cudaGetSymbolAddress((void**)&attnb, g_attnb);
    cudaGetSymbolAddress((void**)&bwin,  g_bwin);
    cudaGetSymbolAddress((void**)&bwout, g_bwout);

    cudaFuncSetAttribute(flash_attn_bf16,
                         cudaFuncAttributeMaxDynamicSharedMemorySize,
                         ATTN_SMEM_BYTES);
    cudaFuncSetAttribute(gemm_bf16_nt,
                         cudaFuncAttributeMaxDynamicSharedMemorySize, GEMM_SMEM_BYTES);
    cudaFuncSetAttribute(gemm_qkv,
                         cudaFuncAttributeMaxDynamicSharedMemorySize, GEMM_SMEM_BYTES);
    cudaFuncSetAttribute(moe_up1,
                         cudaFuncAttributeMaxDynamicSharedMemorySize, GEMM_SMEM_BYTES);
    cudaFuncSetAttribute(moe_up2,
                         cudaFuncAttributeMaxDynamicSharedMemorySize, GEMM_SMEM_BYTES);
    cudaFuncSetAttribute(moe_down,
                         cudaFuncAttributeMaxDynamicSharedMemorySize, GEMM_SMEM_BYTES);

    // fused weight convert + counter init
    f2bf_all<<<3200, 256>>>(in_proj_w, out_proj_w, w1, w2, wo);

    // ---- attention block ----
    layernorm_k<<<SEQ, 128>>>(src, ln1_g, ln1_b, xn, xnb);
    gemm_qkv<<<dim3(12, 32), 256, GEMM_SMEM_BYTES>>>(xnb, bwin, in_proj_b, qkvb,
                                                     SEQ, 3 * DMODEL, DMODEL);
    flash_attn_bf16<<<dim3(SEQ / 128, NHEAD, NSPLIT), 128, ATTN_SMEM_BYTES>>>(qkvb);
    attn_combine<<<SEQ, 128>>>(attnb);
    gemm_bf16_nt<<<dim3(4, 32), 256, GEMM_SMEM_BYTES>>>(attnb, bwout, out_proj_b,
                                                        src, out, SEQ, DMODEL, DMODEL);

    // ---- MoE block ----
    layernorm_k<<<SEQ, 128>>>(out, ln2_g, ln2_b, xn, xnb);
    gate_topk<<<SEQ / 4, 128>>>(xn, gate_w, gate_b);   // fused offsets/tile list
    assign_rows<<<NPAIR / 256, 256>>>();
    moe_up1<<<dim3(FDIM / 128, MAXTILE - 8), 256, GEMM_SMEM_BYTES>>>(b1);
    moe_up2<<<dim3(FDIM / 128, MAXTILE - 8), 256, GEMM_SMEM_BYTES>>>(b2);
    moe_down<<<dim3(DMODEL / 128, MAXTILE - 8), 256, GEMM_SMEM_BYTES>>>(bo);
    moe_combine<<<SEQ, 128>>>(out);
}